// round 6
// baseline (speedup 1.0000x reference)
#include <cuda_runtime.h>
#include <cuda_fp16.h>
#include <cstdint>

#define NNODES 8192
#define EDGES  262144
#define NHEAD  4
#define NEG_FILL -9.0e15f

// ---------------- scratch (no allocations allowed) ----------------
__device__ float  g_Wh1 [NNODES * 256];
__device__ __half g_Wh1h[NNODES * 256];
__device__ float  g_Wh2 [NNODES * 128];
__device__ __half g_Wh2h[NNODES * 128];
__device__ __half g_hHi [NNODES * 256];
__device__ __half g_hLo [NNODES * 256];
__device__ __half g_xHi [NNODES * 256];
__device__ __half g_xLo [NNODES * 256];
__device__ __half g_w1Hi[256 * 256];
__device__ __half g_w1Lo[256 * 256];
__device__ __half g_w2Hi[128 * 256];
__device__ __half g_w2Lo[128 * 256];
__device__ float g_s1src[NHEAD * NNODES];
__device__ float g_s1dst[NHEAD * NNODES];
__device__ float g_s2src[NNODES];
__device__ float g_s2dst[NNODES];
__device__ float g_colsum1[256];
__device__ float g_colsum2[128];
__device__ float g_fill[8];              // [0..3] layer1 heads, [4] layer2
__device__ unsigned g_bitmap[NNODES * NNODES / 32];   // 8 MB dedup bitmap
__device__ int g_deg[NNODES];
__device__ int g_rowptr[NNODES + 1];
__device__ int g_fillptr[NNODES];
__device__ int g_col[EDGES];
__device__ unsigned char g_keep[EDGES];

__device__ __forceinline__ float lrelu(float x) { return x > 0.f ? x : 0.2f * x; }
__device__ __forceinline__ float elu(float x)   { return x > 0.f ? x : expm1f(x); }

__device__ __forceinline__ uint32_t smem_u32(const void* p) {
    uint32_t a;
    asm("{ .reg .u64 t; cvta.to.shared.u64 t, %1; cvt.u32.u64 %0, t; }" : "=r"(a) : "l"(p));
    return a;
}
__device__ __forceinline__ void ldsm4(uint32_t* r, uint32_t addr) {
    asm volatile("ldmatrix.sync.aligned.m8n8.x4.shared.b16 {%0,%1,%2,%3}, [%4];"
                 : "=r"(r[0]), "=r"(r[1]), "=r"(r[2]), "=r"(r[3]) : "r"(addr));
}
__device__ __forceinline__ void mma16816(float* d, const uint32_t* a, uint32_t b0, uint32_t b1) {
    asm volatile("mma.sync.aligned.m16n8k16.row.col.f32.f16.f16.f32 "
                 "{%0,%1,%2,%3}, {%4,%5,%6,%7}, {%8,%9}, {%0,%1,%2,%3};"
                 : "+f"(d[0]), "+f"(d[1]), "+f"(d[2]), "+f"(d[3])
                 : "r"(a[0]), "r"(a[1]), "r"(a[2]), "r"(a[3]), "r"(b0), "r"(b1));
}
__device__ __forceinline__ uint32_t sw_addr(uint32_t base, int row, int chunk) {
    return base + row * 128 + (((chunk ^ (row & 7)) << 4));
}

// ---------------- zero scratch each launch (deterministic) ----------------
__global__ void k_zero() {
    int idx = blockIdx.x * blockDim.x + threadIdx.x;
    if (idx < NNODES * NNODES / 32) g_bitmap[idx] = 0u;
    if (idx < NNODES)  g_deg[idx] = 0;
    if (idx < 256)     g_colsum1[idx] = 0.f;
    if (idx < 128)     g_colsum2[idx] = 0.f;
}

// ---------------- one-time fp32 -> fp16 hi/lo conversion ----------------
__device__ __forceinline__ void cvt4(const float* __restrict__ in, int i4,
                                     __half* __restrict__ hi, __half* __restrict__ lo) {
    float4 v = ((const float4*)in)[i4];
    __half2 h0 = __floats2half2_rn(v.x, v.y);
    __half2 h1 = __floats2half2_rn(v.z, v.w);
    float2 f0 = __half22float2(h0), f1 = __half22float2(h1);
    __half2 l0 = __floats2half2_rn(v.x - f0.x, v.y - f0.y);
    __half2 l1 = __floats2half2_rn(v.z - f1.x, v.w - f1.y);
    ((uint2*)hi)[i4] = make_uint2(*(uint32_t*)&h0, *(uint32_t*)&h1);
    ((uint2*)lo)[i4] = make_uint2(*(uint32_t*)&l0, *(uint32_t*)&l1);
}

__global__ void k_cvt(const float* __restrict__ h,
                      const float* __restrict__ W1,
                      const float* __restrict__ W2) {
    int i = blockIdx.x * blockDim.x + threadIdx.x;   // float4 index
    if (i < NNODES * 256 / 4) cvt4(h, i, g_hHi, g_hLo);
    if (i < 256 * 256 / 4)    cvt4(W1, i, g_w1Hi, g_w1Lo);
    if (i < 128 * 256 / 4)    cvt4(W2, i, g_w2Hi, g_w2Lo);
}

// ---------------- HMMA GEMM on pre-split halves ----------------
// C[M,Nn] = (Ahi+Alo)[M,256] @ (Bhi+Blo)[Nn,256]^T, 128x128 CTA tile,
// 3-MMA hi/lo compensation. Emits fp32 C and fp16 Ch.
__global__ void __launch_bounds__(256) k_gemm_mma(
    const __half* __restrict__ Ahi, const __half* __restrict__ Alo,
    const __half* __restrict__ Bhi, const __half* __restrict__ Blo,
    float* __restrict__ C, __half* __restrict__ Ch, int Nn)
{
    extern __shared__ char smem[];
    uint32_t sb = smem_u32(smem);
    const uint32_t AHI = 0, ALO = 16384, BHI = 32768, BLO = 49152;
    const int tid = threadIdx.x, lane = tid & 31, wid = tid >> 5;
    const int wm = wid & 3, wn = wid >> 2;          // 4 x 2 warp grid
    const int bm = blockIdx.x * 128, bn = blockIdx.y * 128;

    float acc[2][8][4];
#pragma unroll
    for (int i = 0; i < 2; i++)
#pragma unroll
        for (int j = 0; j < 8; j++)
#pragma unroll
            for (int q = 0; q < 4; q++) acc[i][j][q] = 0.f;

    const int g = lane >> 3, lr = lane & 7;

    for (int kc = 0; kc < 4; kc++) {
        // Copy 4 x [128 rows x 64 halfs] chunks into swizzled smem (pure LDG128/STS128).
        const __half* srcs[4] = {Ahi, Alo, Bhi, Blo};
        const uint32_t bases[4] = {AHI, ALO, BHI, BLO};
#pragma unroll
        for (int rgn = 0; rgn < 4; rgn++) {
            const __half* src = srcs[rgn];
            const int rowbase = (rgn < 2) ? bm : bn;
            const uint32_t sbase = bases[rgn];
#pragma unroll
            for (int q = tid; q < 1024; q += 256) {
                int row = q >> 3, c = q & 7;
                uint4 v = *(const uint4*)(src + (size_t)(rowbase + row) * 256 + kc * 64 + c * 8);
                *(uint4*)(smem + sbase + row * 128 + (((c ^ (row & 7)) << 4))) = v;
            }
        }
        __syncthreads();

#pragma unroll
        for (int ks = 0; ks < 4; ks++) {
            const int chunk = ks * 2 + (g >> 1);
            uint32_t ahi[2][4], alo[2][4], bhi[4][4], blo[4][4];
#pragma unroll
            for (int am = 0; am < 2; am++) {
                int row = wm * 32 + am * 16 + (g & 1) * 8 + lr;
                ldsm4(ahi[am], sw_addr(sb + AHI, row, chunk));
                ldsm4(alo[am], sw_addr(sb + ALO, row, chunk));
            }
#pragma unroll
            for (int bp = 0; bp < 4; bp++) {
                int row = wn * 64 + bp * 16 + (g & 1) * 8 + lr;
                ldsm4(bhi[bp], sw_addr(sb + BHI, row, chunk));
                ldsm4(blo[bp], sw_addr(sb + BLO, row, chunk));
            }
#pragma unroll
            for (int am = 0; am < 2; am++)
#pragma unroll
                for (int bp = 0; bp < 4; bp++) {
                    float* c0 = acc[am][bp * 2];
                    float* c1 = acc[am][bp * 2 + 1];
                    mma16816(c0, ahi[am], bhi[bp][0], bhi[bp][2]);
                    mma16816(c1, ahi[am], bhi[bp][1], bhi[bp][3]);
                    mma16816(c0, ahi[am], blo[bp][0], blo[bp][2]);
                    mma16816(c1, ahi[am], blo[bp][1], blo[bp][3]);
                    mma16816(c0, alo[am], bhi[bp][0], bhi[bp][2]);
                    mma16816(c1, alo[am], bhi[bp][1], bhi[bp][3]);
                }
        }
        __syncthreads();
    }

    // epilogue: store C (fp32) + Ch (fp16)
#pragma unroll
    for (int am = 0; am < 2; am++) {
        int r0 = bm + wm * 32 + am * 16 + (lane >> 2);
        int c0 = bn + wn * 64 + (lane & 3) * 2;
#pragma unroll
        for (int j = 0; j < 8; j++) {
            *(float2*)&C[(size_t)r0 * Nn + c0 + j * 8]       = make_float2(acc[am][j][0], acc[am][j][1]);
            *(float2*)&C[(size_t)(r0 + 8) * Nn + c0 + j * 8] = make_float2(acc[am][j][2], acc[am][j][3]);
            __half2 h0 = __floats2half2_rn(acc[am][j][0], acc[am][j][1]);
            __half2 h1 = __floats2half2_rn(acc[am][j][2], acc[am][j][3]);
            *(__half2*)&Ch[(size_t)r0 * Nn + c0 + j * 8]       = h0;
            *(__half2*)&Ch[(size_t)(r0 + 8) * Nn + c0 + j * 8] = h1;
        }
    }
}

// ---------------- fused colsum + per-row attention scalars ----------------
template <int COLS, int HW>
__global__ void __launch_bounds__(256) k_stats(
    const float* __restrict__ Wh, const float* __restrict__ avec,
    float* __restrict__ colsum, float* __restrict__ ssrc, float* __restrict__ sdst)
{
    constexpr int LSPAN = COLS / 32;
    constexpr int SEG   = HW / LSPAN;
    __shared__ float sA[2 * COLS];
    __shared__ float scol[COLS];
    const int tid = threadIdx.x, lane = tid & 31, wid = tid >> 5;

    for (int q = tid; q < COLS; q += 256) {
        int hh = q / HW, d = q % HW;
        sA[q]        = avec[hh * 2 * HW + d];
        sA[COLS + q] = avec[hh * 2 * HW + HW + d];
        scol[q] = 0.f;
    }
    __syncthreads();

    float as[LSPAN], ad[LSPAN], cs[LSPAN];
#pragma unroll
    for (int r = 0; r < LSPAN; r++) {
        as[r] = sA[lane * LSPAN + r];
        ad[r] = sA[COLS + lane * LSPAN + r];
        cs[r] = 0.f;
    }
    const int head = lane / SEG;

    for (int row = blockIdx.x * 8 + wid; row < NNODES; row += gridDim.x * 8) {
        const float* wr = &Wh[(size_t)row * COLS + lane * LSPAN];
        float v[LSPAN];
#pragma unroll
        for (int r = 0; r < LSPAN; r += 4)
            *(float4*)&v[r] = *(const float4*)&wr[r];
        float ps = 0.f, pd = 0.f;
#pragma unroll
        for (int r = 0; r < LSPAN; r++) {
            cs[r] += v[r];
            ps = fmaf(v[r], as[r], ps);
            pd = fmaf(v[r], ad[r], pd);
        }
#pragma unroll
        for (int off = SEG / 2; off; off >>= 1) {
            ps += __shfl_xor_sync(0xffffffffu, ps, off);
            pd += __shfl_xor_sync(0xffffffffu, pd, off);
        }
        if ((lane & (SEG - 1)) == 0) {
            ssrc[(size_t)head * NNODES + row] = ps;
            sdst[(size_t)head * NNODES + row] = pd;
        }
    }
    __syncthreads();
#pragma unroll
    for (int r = 0; r < LSPAN; r++) atomicAdd(&scol[lane * LSPAN + r], cs[r]);
    __syncthreads();
    for (int q = tid; q < COLS; q += 256) atomicAdd(&colsum[q], scol[q]);
}

// ---------------- CSR build with bitmap dedup ----------------
__global__ void k_mark(const int* __restrict__ src, const int* __restrict__ dst) {
    int e = blockIdx.x * blockDim.x + threadIdx.x;
    if (e >= EDGES) return;
    int s = src[e], d = dst[e];
    unsigned idx = (unsigned)s * NNODES + (unsigned)d;
    unsigned mask = 1u << (idx & 31u);
    unsigned old = atomicOr(&g_bitmap[idx >> 5], mask);
    unsigned char keep = (old & mask) ? 0 : 1;
    g_keep[e] = keep;
    if (keep) atomicAdd(&g_deg[s], 1);
}

// 1 block, 1024 threads: exclusive scan of deg[8192] + fill constants
__global__ void k_scan(const float* __restrict__ a1, const float* __restrict__ a2) {
    __shared__ int sh[1024];
    int t = threadIdx.x;
    if (t < 32) {
        int lane = t;
#pragma unroll
        for (int k = 0; k < 4; k++) {
            float s = 0.f;
            for (int d = lane; d < 128; d += 32) s += a1[k * 128 + d];
#pragma unroll
            for (int off = 16; off; off >>= 1) s += __shfl_xor_sync(0xffffffffu, s, off);
            if (lane == 0) g_fill[k] = lrelu(NEG_FILL * s);
        }
        float s = 0.f;
        for (int d = lane; d < 256; d += 32) s += a2[d];
#pragma unroll
        for (int off = 16; off; off >>= 1) s += __shfl_xor_sync(0xffffffffu, s, off);
        if (lane == 0) g_fill[4] = lrelu(NEG_FILL * s);
    }
    int loc[8]; int s = 0;
#pragma unroll
    for (int j = 0; j < 8; j++) { loc[j] = s; s += g_deg[t * 8 + j]; }
    sh[t] = s;
    __syncthreads();
    for (int off = 1; off < 1024; off <<= 1) {
        int v = (t >= off) ? sh[t - off] : 0;
        __syncthreads();
        sh[t] += v;
        __syncthreads();
    }
    int base = (t == 0) ? 0 : sh[t - 1];
#pragma unroll
    for (int j = 0; j < 8; j++) {
        int p = base + loc[j];
        g_rowptr[t * 8 + j] = p;
        g_fillptr[t * 8 + j] = p;
    }
    if (t == 1023) g_rowptr[NNODES] = sh[1023];
}

__global__ void k_fillcsr(const int* __restrict__ src, const int* __restrict__ dst) {
    int e = blockIdx.x * blockDim.x + threadIdx.x;
    if (e >= EDGES) return;
    if (g_keep[e]) {
        int s = src[e];
        int p = atomicAdd(&g_fillptr[s], 1);
        g_col[p] = dst[e];
    }
}

// ---------------- layer-1 aggregation: block per node, warp per head (fp16 gather) ----------------
// Emits layer-2 input directly as hi/lo halves.
__global__ void k_agg1() {
    int i = blockIdx.x;
    int k = threadIdx.x >> 5, lane = threadIdx.x & 31;
    int beg = g_rowptr[i], end = g_rowptr[i + 1];
    float ssrc = g_s1src[k * NNODES + i];
    float fill = g_fill[k];
    float m = fill;
    for (int t = beg + lane; t < end; t += 32) {
        int j = g_col[t];
        m = fmaxf(m, lrelu(ssrc + g_s1dst[k * NNODES + j]));
    }
#pragma unroll
    for (int off = 16; off; off >>= 1) m = fmaxf(m, __shfl_xor_sync(0xffffffffu, m, off));

    float acc0 = 0.f, acc1 = 0.f, an0 = 0.f, an1 = 0.f, ws = 0.f;
    for (int t = beg; t < end; t++) {
        int j = g_col[t];
        float e = lrelu(ssrc + g_s1dst[k * NNODES + j]);
        float wgt = __expf(e - m);
        ws += wgt;
        __half2 v = *(const __half2*)&g_Wh1h[(size_t)j * 256 + k * 64 + 2 * lane];
        float2 vf = __half22float2(v);
        acc0 = fmaf(wgt, vf.x, acc0); acc1 = fmaf(wgt, vf.y, acc1);
        an0 += vf.x; an1 += vf.y;
    }
    float wf = __expf(fill - m);
    int deg = end - beg;
    float denom = ws + (float)(NNODES - deg) * wf;
    float c0 = g_colsum1[k * 64 + 2 * lane], c1 = g_colsum1[k * 64 + 2 * lane + 1];
    float o0 = elu((acc0 + wf * (c0 - an0)) / denom);
    float o1 = elu((acc1 + wf * (c1 - an1)) / denom);
    __half2 hi = __floats2half2_rn(o0, o1);
    float2 hf = __half22float2(hi);
    __half2 lo = __floats2half2_rn(o0 - hf.x, o1 - hf.y);
    size_t off_ = (size_t)i * 256 + k * 64 + 2 * lane;
    *(__half2*)&g_xHi[off_] = hi;
    *(__half2*)&g_xLo[off_] = lo;
}

// ---------------- layer-2 aggregation: warp per node, 128 dims (fp16 gather) ----------------
__global__ void k_agg2(float* __restrict__ out) {
    int i = (blockIdx.x * blockDim.x + threadIdx.x) >> 5;
    int lane = threadIdx.x & 31;
    if (i >= NNODES) return;
    int beg = g_rowptr[i], end = g_rowptr[i + 1];
    float ssrc = g_s2src[i];
    float fill = g_fill[4];
    float m = fill;
    for (int t = beg + lane; t < end; t += 32) {
        int j = g_col[t];
        m = fmaxf(m, lrelu(ssrc + g_s2dst[j]));
    }
#pragma unroll
    for (int off = 16; off; off >>= 1) m = fmaxf(m, __shfl_xor_sync(0xffffffffu, m, off));

    float acc[4] = {0.f, 0.f, 0.f, 0.f}, an[4] = {0.f, 0.f, 0.f, 0.f}, ws = 0.f;
    for (int t = beg; t < end; t++) {
        int j = g_col[t];
        float e = lrelu(ssrc + g_s2dst[j]);
        float wgt = __expf(e - m);
        ws += wgt;
        uint2 u = *(const uint2*)&g_Wh2h[(size_t)j * 128 + 4 * lane];
        float2 va = __half22float2(*(__half2*)&u.x);
        float2 vb = __half22float2(*(__half2*)&u.y);
        acc[0] = fmaf(wgt, va.x, acc[0]); an[0] += va.x;
        acc[1] = fmaf(wgt, va.y, acc[1]); an[1] += va.y;
        acc[2] = fmaf(wgt, vb.x, acc[2]); an[2] += vb.x;
        acc[3] = fmaf(wgt, vb.y, acc[3]); an[3] += vb.y;
    }
    float wf = __expf(fill - m);
    int deg = end - beg;
    float denom = ws + (float)(NNODES - deg) * wf;
#pragma unroll
    for (int r = 0; r < 4; r++) {
        float c = g_colsum2[4 * lane + r];
        float o = (acc[r] + wf * (c - an[r])) / denom;
        o = elu(o);   // head elu
        o = elu(o);   // outer elu
        out[(size_t)i * 128 + 4 * lane + r] = o;
    }
}

// ---------------- launch ----------------
extern "C" void kernel_launch(void* const* d_in, const int* in_sizes, int n_in,
                              void* d_out, int out_size) {
    const float* h   = (const float*)d_in[0];   // [8192,256]
    const float* W1  = (const float*)d_in[1];   // [4,64,256] -> [256,256]
    const float* a1  = (const float*)d_in[2];   // [4,128]
    const float* W2  = (const float*)d_in[3];   // [128,256]
    const float* a2  = (const float*)d_in[4];   // [256]
    const int*  esrc = (const int*)d_in[5];     // [E]
    const int*  edst = (const int*)d_in[6];     // [E]
    float* out = (float*)d_out;

    float *pWh1, *pWh2, *pCs1, *pCs2;
    float *pS1s, *pS1d, *pS2s, *pS2d;
    __half *pWh1h, *pWh2h, *phHi, *phLo, *pxHi, *pxLo, *pw1Hi, *pw1Lo, *pw2Hi, *pw2Lo;
    cudaGetSymbolAddress((void**)&pWh1,  g_Wh1);
    cudaGetSymbolAddress((void**)&pWh1h, g_Wh1h);
    cudaGetSymbolAddress((void**)&pWh2,  g_Wh2);
    cudaGetSymbolAddress((void**)&pWh2h, g_Wh2h);
    cudaGetSymbolAddress((void**)&phHi,  g_hHi);
    cudaGetSymbolAddress((void**)&phLo,  g_hLo);
    cudaGetSymbolAddress((void**)&pxHi,  g_xHi);
    cudaGetSymbolAddress((void**)&pxLo,  g_xLo);
    cudaGetSymbolAddress((void**)&pw1Hi, g_w1Hi);
    cudaGetSymbolAddress((void**)&pw1Lo, g_w1Lo);
    cudaGetSymbolAddress((void**)&pw2Hi, g_w2Hi);
    cudaGetSymbolAddress((void**)&pw2Lo, g_w2Lo);
    cudaGetSymbolAddress((void**)&pCs1,  g_colsum1);
    cudaGetSymbolAddress((void**)&pCs2,  g_colsum2);
    cudaGetSymbolAddress((void**)&pS1s,  g_s1src);
    cudaGetSymbolAddress((void**)&pS1d,  g_s1dst);
    cudaGetSymbolAddress((void**)&pS2s,  g_s2src);
    cudaGetSymbolAddress((void**)&pS2d,  g_s2dst);

    const int SMEM_SZ = 65536;
    cudaFuncSetAttribute(k_gemm_mma, cudaFuncAttributeMaxDynamicSharedMemorySize, SMEM_SZ);

    k_zero<<<2048, 1024>>>();
    k_cvt<<<2048, 256>>>(h, W1, W2);

    // CSR build
    k_mark<<<EDGES / 256, 256>>>(esrc, edst);
    k_scan<<<1, 1024>>>(a1, a2);
    k_fillcsr<<<EDGES / 256, 256>>>(esrc, edst);

    // layer 1
    k_gemm_mma<<<dim3(64, 2), 256, SMEM_SZ>>>(phHi, phLo, pw1Hi, pw1Lo, pWh1, pWh1h, 256);
    k_stats<256, 64><<<128, 256>>>(pWh1, a1, pCs1, pS1s, pS1d);
    k_agg1<<<8192, 128>>>();

    // layer 2
    k_gemm_mma<<<dim3(64, 1), 256, SMEM_SZ>>>(pxHi, pxLo, pw2Hi, pw2Lo, pWh2, pWh2h, 128);
    k_stats<128, 128><<<128, 256>>>(pWh2, a2, pCs2, pS2s, pS2d);
    k_agg2<<<1024, 256>>>(out);
}

// round 7
// speedup vs baseline: 1.0725x; 1.0725x over previous
#include <cuda_runtime.h>
#include <cuda_fp16.h>
#include <cstdint>

#define NNODES 8192
#define EDGES  262144
#define NHEAD  4
#define NEG_FILL -9.0e15f

// ---------------- scratch (no allocations allowed) ----------------
__device__ float  g_Wh1 [NNODES * 256];
__device__ __half g_Wh1h[NNODES * 256];
__device__ float  g_Wh2 [NNODES * 128];
__device__ __half g_Wh2h[NNODES * 128];
__device__ __half g_hHi [NNODES * 256];
__device__ __half g_hLo [NNODES * 256];
__device__ __half g_xHi [NNODES * 256];
__device__ __half g_xLo [NNODES * 256];
__device__ __half g_w1Hi[256 * 256];
__device__ __half g_w1Lo[256 * 256];
__device__ __half g_w2Hi[128 * 256];
__device__ __half g_w2Lo[128 * 256];
__device__ float g_s1src[NHEAD * NNODES];
__device__ float g_s1dst[NHEAD * NNODES];
__device__ float g_s2src[NNODES];
__device__ float g_s2dst[NNODES];
__device__ float g_colsum1[256];
__device__ float g_colsum2[128];
__device__ float g_fill[8];              // [0..3] layer1 heads, [4] layer2
__device__ unsigned g_bitmap[NNODES * NNODES / 32];   // 8 MB dedup bitmap
__device__ int g_deg[NNODES];
__device__ int g_rowptr[NNODES + 1];
__device__ int g_fillptr[NNODES];
__device__ int g_col[EDGES];
__device__ unsigned char g_keep[EDGES];

__device__ __forceinline__ float lrelu(float x) { return x > 0.f ? x : 0.2f * x; }
__device__ __forceinline__ float elu(float x)   { return x > 0.f ? x : expm1f(x); }

__device__ __forceinline__ uint32_t smem_u32(const void* p) {
    uint32_t a;
    asm("{ .reg .u64 t; cvta.to.shared.u64 t, %1; cvt.u32.u64 %0, t; }" : "=r"(a) : "l"(p));
    return a;
}
__device__ __forceinline__ void ldsm4(uint32_t* r, uint32_t addr) {
    asm volatile("ldmatrix.sync.aligned.m8n8.x4.shared.b16 {%0,%1,%2,%3}, [%4];"
                 : "=r"(r[0]), "=r"(r[1]), "=r"(r[2]), "=r"(r[3]) : "r"(addr));
}
__device__ __forceinline__ void mma16816(float* d, const uint32_t* a, uint32_t b0, uint32_t b1) {
    asm volatile("mma.sync.aligned.m16n8k16.row.col.f32.f16.f16.f32 "
                 "{%0,%1,%2,%3}, {%4,%5,%6,%7}, {%8,%9}, {%0,%1,%2,%3};"
                 : "+f"(d[0]), "+f"(d[1]), "+f"(d[2]), "+f"(d[3])
                 : "r"(a[0]), "r"(a[1]), "r"(a[2]), "r"(a[3]), "r"(b0), "r"(b1));
}
__device__ __forceinline__ uint32_t sw_addr(uint32_t base, int row, int chunk) {
    return base + row * 128 + (((chunk ^ (row & 7)) << 4));
}

// ---------------- zero scratch each launch (deterministic) ----------------
__global__ void k_zero() {
    int idx = blockIdx.x * blockDim.x + threadIdx.x;
    if (idx < NNODES * NNODES / 32) g_bitmap[idx] = 0u;
    if (idx < NNODES)  g_deg[idx] = 0;
    if (idx < 256)     g_colsum1[idx] = 0.f;
    if (idx < 128)     g_colsum2[idx] = 0.f;
}

// ---------------- one-time fp32 -> fp16 hi/lo conversion ----------------
__device__ __forceinline__ void cvt4(const float* __restrict__ in, int i4,
                                     __half* __restrict__ hi, __half* __restrict__ lo) {
    float4 v = ((const float4*)in)[i4];
    __half2 h0 = __floats2half2_rn(v.x, v.y);
    __half2 h1 = __floats2half2_rn(v.z, v.w);
    float2 f0 = __half22float2(h0), f1 = __half22float2(h1);
    __half2 l0 = __floats2half2_rn(v.x - f0.x, v.y - f0.y);
    __half2 l1 = __floats2half2_rn(v.z - f1.x, v.w - f1.y);
    ((uint2*)hi)[i4] = make_uint2(*(uint32_t*)&h0, *(uint32_t*)&h1);
    ((uint2*)lo)[i4] = make_uint2(*(uint32_t*)&l0, *(uint32_t*)&l1);
}

__global__ void k_cvt(const float* __restrict__ h,
                      const float* __restrict__ W1,
                      const float* __restrict__ W2) {
    int i = blockIdx.x * blockDim.x + threadIdx.x;   // float4 index
    if (i < NNODES * 256 / 4) cvt4(h, i, g_hHi, g_hLo);
    if (i < 256 * 256 / 4)    cvt4(W1, i, g_w1Hi, g_w1Lo);
    if (i < 128 * 256 / 4)    cvt4(W2, i, g_w2Hi, g_w2Lo);
}

// ---------------- HMMA GEMM on pre-split halves ----------------
__global__ void __launch_bounds__(256) k_gemm_mma(
    const __half* __restrict__ Ahi, const __half* __restrict__ Alo,
    const __half* __restrict__ Bhi, const __half* __restrict__ Blo,
    float* __restrict__ C, __half* __restrict__ Ch, int Nn)
{
    extern __shared__ char smem[];
    uint32_t sb = smem_u32(smem);
    const uint32_t AHI = 0, ALO = 16384, BHI = 32768, BLO = 49152;
    const int tid = threadIdx.x, lane = tid & 31, wid = tid >> 5;
    const int wm = wid & 3, wn = wid >> 2;          // 4 x 2 warp grid
    const int bm = blockIdx.x * 128, bn = blockIdx.y * 128;

    float acc[2][8][4];
#pragma unroll
    for (int i = 0; i < 2; i++)
#pragma unroll
        for (int j = 0; j < 8; j++)
#pragma unroll
            for (int q = 0; q < 4; q++) acc[i][j][q] = 0.f;

    const int g = lane >> 3, lr = lane & 7;

    for (int kc = 0; kc < 4; kc++) {
        const __half* srcs[4] = {Ahi, Alo, Bhi, Blo};
        const uint32_t bases[4] = {AHI, ALO, BHI, BLO};
#pragma unroll
        for (int rgn = 0; rgn < 4; rgn++) {
            const __half* src = srcs[rgn];
            const int rowbase = (rgn < 2) ? bm : bn;
            const uint32_t sbase = bases[rgn];
#pragma unroll
            for (int q = tid; q < 1024; q += 256) {
                int row = q >> 3, c = q & 7;
                uint4 v = *(const uint4*)(src + (size_t)(rowbase + row) * 256 + kc * 64 + c * 8);
                *(uint4*)(smem + sbase + row * 128 + (((c ^ (row & 7)) << 4))) = v;
            }
        }
        __syncthreads();

#pragma unroll
        for (int ks = 0; ks < 4; ks++) {
            const int chunk = ks * 2 + (g >> 1);
            uint32_t ahi[2][4], alo[2][4], bhi[4][4], blo[4][4];
#pragma unroll
            for (int am = 0; am < 2; am++) {
                int row = wm * 32 + am * 16 + (g & 1) * 8 + lr;
                ldsm4(ahi[am], sw_addr(sb + AHI, row, chunk));
                ldsm4(alo[am], sw_addr(sb + ALO, row, chunk));
            }
#pragma unroll
            for (int bp = 0; bp < 4; bp++) {
                int row = wn * 64 + bp * 16 + (g & 1) * 8 + lr;
                ldsm4(bhi[bp], sw_addr(sb + BHI, row, chunk));
                ldsm4(blo[bp], sw_addr(sb + BLO, row, chunk));
            }
#pragma unroll
            for (int am = 0; am < 2; am++)
#pragma unroll
                for (int bp = 0; bp < 4; bp++) {
                    float* c0 = acc[am][bp * 2];
                    float* c1 = acc[am][bp * 2 + 1];
                    mma16816(c0, ahi[am], bhi[bp][0], bhi[bp][2]);
                    mma16816(c1, ahi[am], bhi[bp][1], bhi[bp][3]);
                    mma16816(c0, ahi[am], blo[bp][0], blo[bp][2]);
                    mma16816(c1, ahi[am], blo[bp][1], blo[bp][3]);
                    mma16816(c0, alo[am], bhi[bp][0], bhi[bp][2]);
                    mma16816(c1, alo[am], bhi[bp][1], bhi[bp][3]);
                }
        }
        __syncthreads();
    }

    // epilogue: store C (fp32) + Ch (fp16)
#pragma unroll
    for (int am = 0; am < 2; am++) {
        int r0 = bm + wm * 32 + am * 16 + (lane >> 2);
        int c0 = bn + wn * 64 + (lane & 3) * 2;
#pragma unroll
        for (int j = 0; j < 8; j++) {
            *(float2*)&C[(size_t)r0 * Nn + c0 + j * 8]       = make_float2(acc[am][j][0], acc[am][j][1]);
            *(float2*)&C[(size_t)(r0 + 8) * Nn + c0 + j * 8] = make_float2(acc[am][j][2], acc[am][j][3]);
            __half2 h0 = __floats2half2_rn(acc[am][j][0], acc[am][j][1]);
            __half2 h1 = __floats2half2_rn(acc[am][j][2], acc[am][j][3]);
            *(__half2*)&Ch[(size_t)r0 * Nn + c0 + j * 8]       = h0;
            *(__half2*)&Ch[(size_t)(r0 + 8) * Nn + c0 + j * 8] = h1;
        }
    }
}

// ---------------- fused colsum + per-row attention scalars ----------------
template <int COLS, int HW>
__global__ void __launch_bounds__(256) k_stats(
    const float* __restrict__ Wh, const float* __restrict__ avec,
    float* __restrict__ colsum, float* __restrict__ ssrc, float* __restrict__ sdst)
{
    constexpr int LSPAN = COLS / 32;
    constexpr int SEG   = HW / LSPAN;
    __shared__ float sA[2 * COLS];
    __shared__ float scol[COLS];
    const int tid = threadIdx.x, lane = tid & 31, wid = tid >> 5;

    for (int q = tid; q < COLS; q += 256) {
        int hh = q / HW, d = q % HW;
        sA[q]        = avec[hh * 2 * HW + d];
        sA[COLS + q] = avec[hh * 2 * HW + HW + d];
        scol[q] = 0.f;
    }
    __syncthreads();

    float as[LSPAN], ad[LSPAN], cs[LSPAN];
#pragma unroll
    for (int r = 0; r < LSPAN; r++) {
        as[r] = sA[lane * LSPAN + r];
        ad[r] = sA[COLS + lane * LSPAN + r];
        cs[r] = 0.f;
    }
    const int head = lane / SEG;

    for (int row = blockIdx.x * 8 + wid; row < NNODES; row += gridDim.x * 8) {
        const float* wr = &Wh[(size_t)row * COLS + lane * LSPAN];
        float v[LSPAN];
#pragma unroll
        for (int r = 0; r < LSPAN; r += 4)
            *(float4*)&v[r] = *(const float4*)&wr[r];
        float ps = 0.f, pd = 0.f;
#pragma unroll
        for (int r = 0; r < LSPAN; r++) {
            cs[r] += v[r];
            ps = fmaf(v[r], as[r], ps);
            pd = fmaf(v[r], ad[r], pd);
        }
#pragma unroll
        for (int off = SEG / 2; off; off >>= 1) {
            ps += __shfl_xor_sync(0xffffffffu, ps, off);
            pd += __shfl_xor_sync(0xffffffffu, pd, off);
        }
        if ((lane & (SEG - 1)) == 0) {
            ssrc[(size_t)head * NNODES + row] = ps;
            sdst[(size_t)head * NNODES + row] = pd;
        }
    }
    __syncthreads();
#pragma unroll
    for (int r = 0; r < LSPAN; r++) atomicAdd(&scol[lane * LSPAN + r], cs[r]);
    __syncthreads();
    for (int q = tid; q < COLS; q += 256) atomicAdd(&colsum[q], scol[q]);
}

// ---------------- CSR build with bitmap dedup ----------------
__global__ void k_mark(const int* __restrict__ src, const int* __restrict__ dst) {
    int e = blockIdx.x * blockDim.x + threadIdx.x;
    if (e >= EDGES) return;
    int s = src[e], d = dst[e];
    unsigned idx = (unsigned)s * NNODES + (unsigned)d;
    unsigned mask = 1u << (idx & 31u);
    unsigned old = atomicOr(&g_bitmap[idx >> 5], mask);
    unsigned char keep = (old & mask) ? 0 : 1;
    g_keep[e] = keep;
    if (keep) atomicAdd(&g_deg[s], 1);
}

// 1 block, 256 threads: fast exclusive scan of deg[8192] + fill constants
__global__ void k_scan(const float* __restrict__ a1, const float* __restrict__ a2) {
    __shared__ int wsum[8];
    int t = threadIdx.x;
    if (t < 32) {
        int lane = t;
#pragma unroll
        for (int k = 0; k < 4; k++) {
            float s = 0.f;
            for (int d = lane; d < 128; d += 32) s += a1[k * 128 + d];
#pragma unroll
            for (int off = 16; off; off >>= 1) s += __shfl_xor_sync(0xffffffffu, s, off);
            if (lane == 0) g_fill[k] = lrelu(NEG_FILL * s);
        }
        float s = 0.f;
        for (int d = lane; d < 256; d += 32) s += a2[d];
#pragma unroll
        for (int off = 16; off; off >>= 1) s += __shfl_xor_sync(0xffffffffu, s, off);
        if (lane == 0) g_fill[4] = lrelu(NEG_FILL * s);
    }
    // 32 elements per thread
    int loc[32];
    const int base = t * 32;
    int s = 0;
#pragma unroll
    for (int q = 0; q < 8; q++) {
        int4 w = *(const int4*)&g_deg[base + q * 4];
        loc[q * 4 + 0] = s; s += w.x;
        loc[q * 4 + 1] = s; s += w.y;
        loc[q * 4 + 2] = s; s += w.z;
        loc[q * 4 + 3] = s; s += w.w;
    }
    const int lane = t & 31, wid = t >> 5;
    int inc = s;
#pragma unroll
    for (int off = 1; off < 32; off <<= 1) {
        int n_ = __shfl_up_sync(0xffffffffu, inc, off);
        if (lane >= off) inc += n_;
    }
    if (lane == 31) wsum[wid] = inc;
    __syncthreads();
    if (t == 0) {
        int acc = 0;
#pragma unroll
        for (int w = 0; w < 8; w++) { int x = wsum[w]; wsum[w] = acc; acc += x; }
        g_rowptr[NNODES] = acc;
    }
    __syncthreads();
    const int mybase = wsum[wid] + inc - s;
#pragma unroll
    for (int q = 0; q < 8; q++) {
        int4 r = make_int4(mybase + loc[q * 4 + 0], mybase + loc[q * 4 + 1],
                           mybase + loc[q * 4 + 2], mybase + loc[q * 4 + 3]);
        *(int4*)&g_rowptr[base + q * 4]  = r;
        *(int4*)&g_fillptr[base + q * 4] = r;
    }
}

__global__ void k_fillcsr(const int* __restrict__ src, const int* __restrict__ dst) {
    int e = blockIdx.x * blockDim.x + threadIdx.x;
    if (e >= EDGES) return;
    if (g_keep[e]) {
        int s = src[e];
        int p = atomicAdd(&g_fillptr[s], 1);
        g_col[p] = dst[e];
    }
}

// ---------------- layer-1 aggregation: single pass (m = max(fill,0)) ----------------
__global__ void k_agg1() {
    int i = blockIdx.x;
    int k = threadIdx.x >> 5, lane = threadIdx.x & 31;
    int beg = g_rowptr[i], end = g_rowptr[i + 1];
    int deg = end - beg;
    float c0 = g_colsum1[k * 64 + 2 * lane], c1 = g_colsum1[k * 64 + 2 * lane + 1];
    float o0, o1;
    if (deg == 0) {
        o0 = c0 * (1.f / NNODES);
        o1 = c1 * (1.f / NNODES);
    } else {
        float ssrc = g_s1src[k * NNODES + i];
        float fill = g_fill[k];
        float m = fmaxf(fill, 0.f);
        float acc0 = 0.f, acc1 = 0.f, an0 = 0.f, an1 = 0.f, ws = 0.f;
        for (int t = beg; t < end; t++) {
            int j = g_col[t];
            float e = lrelu(ssrc + g_s1dst[k * NNODES + j]);
            float wgt = __expf(e - m);
            ws += wgt;
            __half2 v = *(const __half2*)&g_Wh1h[(size_t)j * 256 + k * 64 + 2 * lane];
            float2 vf = __half22float2(v);
            acc0 = fmaf(wgt, vf.x, acc0); acc1 = fmaf(wgt, vf.y, acc1);
            an0 += vf.x; an1 += vf.y;
        }
        float wf = __expf(fill - m);
        float denom = ws + (float)(NNODES - deg) * wf;
        o0 = (acc0 + wf * (c0 - an0)) / denom;
        o1 = (acc1 + wf * (c1 - an1)) / denom;
    }
    o0 = elu(o0); o1 = elu(o1);
    __half2 hi = __floats2half2_rn(o0, o1);
    float2 hf = __half22float2(hi);
    __half2 lo = __floats2half2_rn(o0 - hf.x, o1 - hf.y);
    size_t off_ = (size_t)i * 256 + k * 64 + 2 * lane;
    *(__half2*)&g_xHi[off_] = hi;
    *(__half2*)&g_xLo[off_] = lo;
}

// ---------------- layer-2 aggregation: single pass, warp per node ----------------
__global__ void k_agg2(float* __restrict__ out) {
    int i = (blockIdx.x * blockDim.x + threadIdx.x) >> 5;
    int lane = threadIdx.x & 31;
    if (i >= NNODES) return;
    int beg = g_rowptr[i], end = g_rowptr[i + 1];
    int deg = end - beg;
    float o[4];
    if (deg == 0) {
#pragma unroll
        for (int r = 0; r < 4; r++) o[r] = g_colsum2[4 * lane + r] * (1.f / NNODES);
    } else {
        float ssrc = g_s2src[i];
        float fill = g_fill[4];
        float m = fmaxf(fill, 0.f);
        float acc[4] = {0.f, 0.f, 0.f, 0.f}, an[4] = {0.f, 0.f, 0.f, 0.f}, ws = 0.f;
        for (int t = beg; t < end; t++) {
            int j = g_col[t];
            float e = lrelu(ssrc + g_s2dst[j]);
            float wgt = __expf(e - m);
            ws += wgt;
            uint2 u = *(const uint2*)&g_Wh2h[(size_t)j * 128 + 4 * lane];
            float2 va = __half22float2(*(__half2*)&u.x);
            float2 vb = __half22float2(*(__half2*)&u.y);
            acc[0] = fmaf(wgt, va.x, acc[0]); an[0] += va.x;
            acc[1] = fmaf(wgt, va.y, acc[1]); an[1] += va.y;
            acc[2] = fmaf(wgt, vb.x, acc[2]); an[2] += vb.x;
            acc[3] = fmaf(wgt, vb.y, acc[3]); an[3] += vb.y;
        }
        float wf = __expf(fill - m);
        float denom = ws + (float)(NNODES - deg) * wf;
#pragma unroll
        for (int r = 0; r < 4; r++)
            o[r] = (acc[r] + wf * (g_colsum2[4 * lane + r] - an[r])) / denom;
    }
#pragma unroll
    for (int r = 0; r < 4; r++)
        out[(size_t)i * 128 + 4 * lane + r] = elu(elu(o[r]));
}

// ---------------- launch ----------------
extern "C" void kernel_launch(void* const* d_in, const int* in_sizes, int n_in,
                              void* d_out, int out_size) {
    const float* h   = (const float*)d_in[0];   // [8192,256]
    const float* W1  = (const float*)d_in[1];   // [4,64,256] -> [256,256]
    const float* a1  = (const float*)d_in[2];   // [4,128]
    const float* W2  = (const float*)d_in[3];   // [128,256]
    const float* a2  = (const float*)d_in[4];   // [256]
    const int*  esrc = (const int*)d_in[5];     // [E]
    const int*  edst = (const int*)d_in[6];     // [E]
    float* out = (float*)d_out;

    float *pWh1, *pWh2, *pCs1, *pCs2;
    float *pS1s, *pS1d, *pS2s, *pS2d;
    __half *pWh1h, *pWh2h, *phHi, *phLo, *pxHi, *pxLo, *pw1Hi, *pw1Lo, *pw2Hi, *pw2Lo;
    cudaGetSymbolAddress((void**)&pWh1,  g_Wh1);
    cudaGetSymbolAddress((void**)&pWh1h, g_Wh1h);
    cudaGetSymbolAddress((void**)&pWh2,  g_Wh2);
    cudaGetSymbolAddress((void**)&pWh2h, g_Wh2h);
    cudaGetSymbolAddress((void**)&phHi,  g_hHi);
    cudaGetSymbolAddress((void**)&phLo,  g_hLo);
    cudaGetSymbolAddress((void**)&pxHi,  g_xHi);
    cudaGetSymbolAddress((void**)&pxLo,  g_xLo);
    cudaGetSymbolAddress((void**)&pw1Hi, g_w1Hi);
    cudaGetSymbolAddress((void**)&pw1Lo, g_w1Lo);
    cudaGetSymbolAddress((void**)&pw2Hi, g_w2Hi);
    cudaGetSymbolAddress((void**)&pw2Lo, g_w2Lo);
    cudaGetSymbolAddress((void**)&pCs1,  g_colsum1);
    cudaGetSymbolAddress((void**)&pCs2,  g_colsum2);
    cudaGetSymbolAddress((void**)&pS1s,  g_s1src);
    cudaGetSymbolAddress((void**)&pS1d,  g_s1dst);
    cudaGetSymbolAddress((void**)&pS2s,  g_s2src);
    cudaGetSymbolAddress((void**)&pS2d,  g_s2dst);

    const int SMEM_SZ = 65536;
    cudaFuncSetAttribute(k_gemm_mma, cudaFuncAttributeMaxDynamicSharedMemorySize, SMEM_SZ);

    k_zero<<<2048, 1024>>>();
    k_cvt<<<2048, 256>>>(h, W1, W2);

    // CSR build
    k_mark<<<EDGES / 256, 256>>>(esrc, edst);
    k_scan<<<1, 256>>>(a1, a2);
    k_fillcsr<<<EDGES / 256, 256>>>(esrc, edst);

    // layer 1
    k_gemm_mma<<<dim3(64, 2), 256, SMEM_SZ>>>(phHi, phLo, pw1Hi, pw1Lo, pWh1, pWh1h, 256);
    k_stats<256, 64><<<128, 256>>>(pWh1, a1, pCs1, pS1s, pS1d);
    k_agg1<<<8192, 128>>>();

    // layer 2
    k_gemm_mma<<<dim3(64, 1), 256, SMEM_SZ>>>(pxHi, pxLo, pw2Hi, pw2Lo, pWh2, pWh2h, 128);
    k_stats<128, 128><<<128, 256>>>(pWh2, a2, pCs2, pS2s, pS2d);
    k_agg2<<<1024, 256>>>(out);
}

// round 8
// speedup vs baseline: 1.1911x; 1.1105x over previous
#include <cuda_runtime.h>
#include <cuda_fp16.h>
#include <cstdint>

#define NNODES 8192
#define EDGES  262144
#define NHEAD  4
#define NEG_FILL -9.0e15f
#define BCAP 128

// ---------------- scratch (no allocations allowed) ----------------
__device__ __half g_Wh1h[NNODES * 256];
__device__ __half g_Wh2h[NNODES * 128];
__device__ __half g_hHi [NNODES * 256];
__device__ __half g_hLo [NNODES * 256];
__device__ __half g_xHi [NNODES * 256];
__device__ __half g_xLo [NNODES * 256];
__device__ __half g_w1Hi[256 * 256];
__device__ __half g_w1Lo[256 * 256];
__device__ __half g_w2Hi[128 * 256];
__device__ __half g_w2Lo[128 * 256];
__device__ float g_s1src[NHEAD * NNODES];
__device__ float g_s1dst[NHEAD * NNODES];
__device__ float g_s2src[NNODES];
__device__ float g_s2dst[NNODES];
__device__ float g_colsum1[256];
__device__ float g_colsum2[128];
__device__ float g_fill[8];              // [0..3] layer1 heads, [4] layer2
__device__ unsigned g_bitmap[NNODES * NNODES / 32];   // 8 MB dedup bitmap
__device__ int g_deg[NNODES];
__device__ int g_bucket[NNODES * BCAP];  // 4 MB neighbor buckets

__device__ __forceinline__ float lrelu(float x) { return x > 0.f ? x : 0.2f * x; }
__device__ __forceinline__ float elu(float x)   { return x > 0.f ? x : expm1f(x); }

__device__ __forceinline__ uint32_t smem_u32(const void* p) {
    uint32_t a;
    asm("{ .reg .u64 t; cvta.to.shared.u64 t, %1; cvt.u32.u64 %0, t; }" : "=r"(a) : "l"(p));
    return a;
}
__device__ __forceinline__ void ldsm4(uint32_t* r, uint32_t addr) {
    asm volatile("ldmatrix.sync.aligned.m8n8.x4.shared.b16 {%0,%1,%2,%3}, [%4];"
                 : "=r"(r[0]), "=r"(r[1]), "=r"(r[2]), "=r"(r[3]) : "r"(addr));
}
__device__ __forceinline__ void mma16816(float* d, const uint32_t* a, uint32_t b0, uint32_t b1) {
    asm volatile("mma.sync.aligned.m16n8k16.row.col.f32.f16.f16.f32 "
                 "{%0,%1,%2,%3}, {%4,%5,%6,%7}, {%8,%9}, {%0,%1,%2,%3};"
                 : "+f"(d[0]), "+f"(d[1]), "+f"(d[2]), "+f"(d[3])
                 : "r"(a[0]), "r"(a[1]), "r"(a[2]), "r"(a[3]), "r"(b0), "r"(b1));
}
__device__ __forceinline__ uint32_t sw_addr(uint32_t base, int row, int chunk) {
    return base + row * 128 + (((chunk ^ (row & 7)) << 4));
}

// ---------------- zero scratch + fill constants (one kernel) ----------------
__global__ void k_zero(const float* __restrict__ a1, const float* __restrict__ a2) {
    int idx = blockIdx.x * blockDim.x + threadIdx.x;      // 512 x 1024 = 524288
    ((uint4*)g_bitmap)[idx] = make_uint4(0u, 0u, 0u, 0u);
    float4 z = make_float4(0.f, 0.f, 0.f, 0.f);
    if (idx < NNODES / 4) ((int4*)g_deg)[idx] = make_int4(0, 0, 0, 0);
    if (idx < 64) ((float4*)g_colsum1)[idx] = z;
    if (idx < 32) ((float4*)g_colsum2)[idx] = z;
    if (idx < NHEAD * NNODES / 4) { ((float4*)g_s1src)[idx] = z; ((float4*)g_s1dst)[idx] = z; }
    if (idx < NNODES / 4) { ((float4*)g_s2src)[idx] = z; ((float4*)g_s2dst)[idx] = z; }
    if (blockIdx.x == 0 && threadIdx.x < 32) {
        int lane = threadIdx.x;
#pragma unroll
        for (int k = 0; k < 4; k++) {
            float s = 0.f;
            for (int d = lane; d < 128; d += 32) s += a1[k * 128 + d];
#pragma unroll
            for (int off = 16; off; off >>= 1) s += __shfl_xor_sync(0xffffffffu, s, off);
            if (lane == 0) g_fill[k] = lrelu(NEG_FILL * s);
        }
        float s = 0.f;
        for (int d = lane; d < 256; d += 32) s += a2[d];
#pragma unroll
        for (int off = 16; off; off >>= 1) s += __shfl_xor_sync(0xffffffffu, s, off);
        if (lane == 0) g_fill[4] = lrelu(NEG_FILL * s);
    }
}

// ---------------- one-time fp32 -> fp16 hi/lo conversion ----------------
__device__ __forceinline__ void cvt4(const float* __restrict__ in, int i4,
                                     __half* __restrict__ hi, __half* __restrict__ lo) {
    float4 v = ((const float4*)in)[i4];
    __half2 h0 = __floats2half2_rn(v.x, v.y);
    __half2 h1 = __floats2half2_rn(v.z, v.w);
    float2 f0 = __half22float2(h0), f1 = __half22float2(h1);
    __half2 l0 = __floats2half2_rn(v.x - f0.x, v.y - f0.y);
    __half2 l1 = __floats2half2_rn(v.z - f1.x, v.w - f1.y);
    ((uint2*)hi)[i4] = make_uint2(*(uint32_t*)&h0, *(uint32_t*)&h1);
    ((uint2*)lo)[i4] = make_uint2(*(uint32_t*)&l0, *(uint32_t*)&l1);
}

__global__ void k_cvt(const float* __restrict__ h,
                      const float* __restrict__ W1,
                      const float* __restrict__ W2) {
    int i = blockIdx.x * blockDim.x + threadIdx.x;   // float4 index
    if (i < NNODES * 256 / 4) cvt4(h, i, g_hHi, g_hLo);
    if (i < 256 * 256 / 4)    cvt4(W1, i, g_w1Hi, g_w1Lo);
    if (i < 128 * 256 / 4)    cvt4(W2, i, g_w2Hi, g_w2Lo);
}

// ---------------- edge dedup + direct bucket CSR ----------------
__global__ void k_mark(const int* __restrict__ src, const int* __restrict__ dst) {
    int e = blockIdx.x * blockDim.x + threadIdx.x;
    if (e >= EDGES) return;
    int s = src[e], d = dst[e];
    unsigned idx = (unsigned)s * NNODES + (unsigned)d;
    unsigned mask = 1u << (idx & 31u);
    unsigned old = atomicOr(&g_bitmap[idx >> 5], mask);
    if (!(old & mask)) {
        int slot = atomicAdd(&g_deg[s], 1);
        g_bucket[s * BCAP + slot] = d;
    }
}

// ---------------- HMMA GEMM + fused stats epilogue ----------------
// C = (Ahi+Alo)[M,256] @ (Bhi+Blo)[Nn,256]^T; emits fp16 Ch, per-row attention
// scalars (atomic, pre-zeroed) and column sums (atomic, pre-zeroed).
template <int HW>
__global__ void __launch_bounds__(256) k_gemm_mma(
    const __half* __restrict__ Ahi, const __half* __restrict__ Alo,
    const __half* __restrict__ Bhi, const __half* __restrict__ Blo,
    __half* __restrict__ Ch, const float* __restrict__ avec,
    float* __restrict__ ssrc, float* __restrict__ sdst,
    float* __restrict__ colsum, int Nn)
{
    extern __shared__ char smem[];
    uint32_t sb = smem_u32(smem);
    const uint32_t AHI = 0, ALO = 16384, BHI = 32768, BLO = 49152;
    const int tid = threadIdx.x, lane = tid & 31, wid = tid >> 5;
    const int wm = wid & 3, wn = wid >> 2;          // 4 x 2 warp grid
    const int bm = blockIdx.x * 128, bn = blockIdx.y * 128;

    float acc[2][8][4];
#pragma unroll
    for (int i = 0; i < 2; i++)
#pragma unroll
        for (int j = 0; j < 8; j++)
#pragma unroll
            for (int q = 0; q < 4; q++) acc[i][j][q] = 0.f;

    const int g = lane >> 3, lr = lane & 7;

    for (int kc = 0; kc < 4; kc++) {
        const __half* srcs[4] = {Ahi, Alo, Bhi, Blo};
        const uint32_t bases[4] = {AHI, ALO, BHI, BLO};
#pragma unroll
        for (int rgn = 0; rgn < 4; rgn++) {
            const __half* src = srcs[rgn];
            const int rowbase = (rgn < 2) ? bm : bn;
            const uint32_t sbase = bases[rgn];
#pragma unroll
            for (int q = tid; q < 1024; q += 256) {
                int row = q >> 3, c = q & 7;
                uint4 v = *(const uint4*)(src + (size_t)(rowbase + row) * 256 + kc * 64 + c * 8);
                *(uint4*)(smem + sbase + row * 128 + (((c ^ (row & 7)) << 4))) = v;
            }
        }
        __syncthreads();

#pragma unroll
        for (int ks = 0; ks < 4; ks++) {
            const int chunk = ks * 2 + (g >> 1);
            uint32_t ahi[2][4], alo[2][4], bhi[4][4], blo[4][4];
#pragma unroll
            for (int am = 0; am < 2; am++) {
                int row = wm * 32 + am * 16 + (g & 1) * 8 + lr;
                ldsm4(ahi[am], sw_addr(sb + AHI, row, chunk));
                ldsm4(alo[am], sw_addr(sb + ALO, row, chunk));
            }
#pragma unroll
            for (int bp = 0; bp < 4; bp++) {
                int row = wn * 64 + bp * 16 + (g & 1) * 8 + lr;
                ldsm4(bhi[bp], sw_addr(sb + BHI, row, chunk));
                ldsm4(blo[bp], sw_addr(sb + BLO, row, chunk));
            }
#pragma unroll
            for (int am = 0; am < 2; am++)
#pragma unroll
                for (int bp = 0; bp < 4; bp++) {
                    float* c0 = acc[am][bp * 2];
                    float* c1 = acc[am][bp * 2 + 1];
                    mma16816(c0, ahi[am], bhi[bp][0], bhi[bp][2]);
                    mma16816(c1, ahi[am], bhi[bp][1], bhi[bp][3]);
                    mma16816(c0, ahi[am], blo[bp][0], blo[bp][2]);
                    mma16816(c1, ahi[am], blo[bp][1], blo[bp][3]);
                    mma16816(c0, alo[am], bhi[bp][0], bhi[bp][2]);
                    mma16816(c1, alo[am], bhi[bp][1], bhi[bp][3]);
                }
        }
        __syncthreads();
    }

    // ---- epilogue: fp16 store + fused stats ----
    const int head = (bn + wn * 64) / HW;
    const int cbase = ((wn * 64) % HW) + (lane & 3) * 2;
    float aS[16], aD[16];
#pragma unroll
    for (int j = 0; j < 8; j++)
#pragma unroll
        for (int p = 0; p < 2; p++) {
            int cc = cbase + j * 8 + p;
            aS[j * 2 + p] = __ldg(&avec[head * 2 * HW + cc]);
            aD[j * 2 + p] = __ldg(&avec[head * 2 * HW + HW + cc]);
        }
    float ps[4] = {0.f, 0.f, 0.f, 0.f}, pd[4] = {0.f, 0.f, 0.f, 0.f}, cs[16];
#pragma unroll
    for (int c = 0; c < 16; c++) cs[c] = 0.f;

#pragma unroll
    for (int am = 0; am < 2; am++) {
        int r0 = bm + wm * 32 + am * 16 + (lane >> 2);
        int c0 = bn + wn * 64 + (lane & 3) * 2;
#pragma unroll
        for (int j = 0; j < 8; j++) {
            __half2 h0 = __floats2half2_rn(acc[am][j][0], acc[am][j][1]);
            __half2 h1 = __floats2half2_rn(acc[am][j][2], acc[am][j][3]);
            *(__half2*)&Ch[(size_t)r0 * Nn + c0 + j * 8]       = h0;
            *(__half2*)&Ch[(size_t)(r0 + 8) * Nn + c0 + j * 8] = h1;
#pragma unroll
            for (int q = 0; q < 4; q++) {
                float v = acc[am][j][q];
                int ridx = am * 2 + (q >> 1);
                int cidx = j * 2 + (q & 1);
                ps[ridx] = fmaf(v, aS[cidx], ps[ridx]);
                pd[ridx] = fmaf(v, aD[cidx], pd[ridx]);
                cs[cidx] += v;
            }
        }
    }
    // row scalars: reduce over lane&3 group
#pragma unroll
    for (int off = 1; off <= 2; off <<= 1)
#pragma unroll
        for (int r = 0; r < 4; r++) {
            ps[r] += __shfl_xor_sync(0xffffffffu, ps[r], off);
            pd[r] += __shfl_xor_sync(0xffffffffu, pd[r], off);
        }
    if ((lane & 3) == 0) {
#pragma unroll
        for (int r = 0; r < 4; r++) {
            int row = bm + wm * 32 + (r >> 1) * 16 + (lane >> 2) + (r & 1) * 8;
            atomicAdd(&ssrc[(size_t)head * NNODES + row], ps[r]);
            atomicAdd(&sdst[(size_t)head * NNODES + row], pd[r]);
        }
    }
    // column sums: reduce over lane>>2 (preserves lane&3)
#pragma unroll
    for (int off = 4; off <= 16; off <<= 1)
#pragma unroll
        for (int c = 0; c < 16; c++) cs[c] += __shfl_xor_sync(0xffffffffu, cs[c], off);
    if (lane < 4) {
#pragma unroll
        for (int j = 0; j < 8; j++)
#pragma unroll
            for (int p = 0; p < 2; p++) {
                int col = bn + wn * 64 + lane * 2 + j * 8 + p;
                atomicAdd(&colsum[col], cs[j * 2 + p]);
            }
    }
}

// ---------------- layer-1 aggregation: block per node, warp per head ----------------
__global__ void k_agg1() {
    int i = blockIdx.x;
    int k = threadIdx.x >> 5, lane = threadIdx.x & 31;
    int deg = g_deg[i];
    const int* bkt = &g_bucket[i * BCAP];
    float c0 = g_colsum1[k * 64 + 2 * lane], c1 = g_colsum1[k * 64 + 2 * lane + 1];
    float o0, o1;
    if (deg == 0) {
        o0 = c0 * (1.f / NNODES);
        o1 = c1 * (1.f / NNODES);
    } else {
        float ssrc = g_s1src[k * NNODES + i];
        float fill = g_fill[k];
        float m = fmaxf(fill, 0.f);
        float acc0 = 0.f, acc1 = 0.f, an0 = 0.f, an1 = 0.f, ws = 0.f;
        for (int t = 0; t < deg; t++) {
            int j = bkt[t];
            float e = lrelu(ssrc + g_s1dst[k * NNODES + j]);
            float wgt = __expf(e - m);
            ws += wgt;
            __half2 v = *(const __half2*)&g_Wh1h[(size_t)j * 256 + k * 64 + 2 * lane];
            float2 vf = __half22float2(v);
            acc0 = fmaf(wgt, vf.x, acc0); acc1 = fmaf(wgt, vf.y, acc1);
            an0 += vf.x; an1 += vf.y;
        }
        float wf = __expf(fill - m);
        float denom = ws + (float)(NNODES - deg) * wf;
        o0 = (acc0 + wf * (c0 - an0)) / denom;
        o1 = (acc1 + wf * (c1 - an1)) / denom;
    }
    o0 = elu(o0); o1 = elu(o1);
    __half2 hi = __floats2half2_rn(o0, o1);
    float2 hf = __half22float2(hi);
    __half2 lo = __floats2half2_rn(o0 - hf.x, o1 - hf.y);
    size_t off_ = (size_t)i * 256 + k * 64 + 2 * lane;
    *(__half2*)&g_xHi[off_] = hi;
    *(__half2*)&g_xLo[off_] = lo;
}

// ---------------- layer-2 aggregation: warp per node ----------------
__global__ void k_agg2(float* __restrict__ out) {
    int i = (blockIdx.x * blockDim.x + threadIdx.x) >> 5;
    int lane = threadIdx.x & 31;
    if (i >= NNODES) return;
    int deg = g_deg[i];
    const int* bkt = &g_bucket[i * BCAP];
    float o[4];
    if (deg == 0) {
#pragma unroll
        for (int r = 0; r < 4; r++) o[r] = g_colsum2[4 * lane + r] * (1.f / NNODES);
    } else {
        float ssrc = g_s2src[i];
        float fill = g_fill[4];
        float m = fmaxf(fill, 0.f);
        float acc[4] = {0.f, 0.f, 0.f, 0.f}, an[4] = {0.f, 0.f, 0.f, 0.f}, ws = 0.f;
        for (int t = 0; t < deg; t++) {
            int j = bkt[t];
            float e = lrelu(ssrc + g_s2dst[j]);
            float wgt = __expf(e - m);
            ws += wgt;
            uint2 u = *(const uint2*)&g_Wh2h[(size_t)j * 128 + 4 * lane];
            float2 va = __half22float2(*(__half2*)&u.x);
            float2 vb = __half22float2(*(__half2*)&u.y);
            acc[0] = fmaf(wgt, va.x, acc[0]); an[0] += va.x;
            acc[1] = fmaf(wgt, va.y, acc[1]); an[1] += va.y;
            acc[2] = fmaf(wgt, vb.x, acc[2]); an[2] += vb.x;
            acc[3] = fmaf(wgt, vb.y, acc[3]); an[3] += vb.y;
        }
        float wf = __expf(fill - m);
        float denom = ws + (float)(NNODES - deg) * wf;
#pragma unroll
        for (int r = 0; r < 4; r++)
            o[r] = (acc[r] + wf * (g_colsum2[4 * lane + r] - an[r])) / denom;
    }
#pragma unroll
    for (int r = 0; r < 4; r++)
        out[(size_t)i * 128 + 4 * lane + r] = elu(elu(o[r]));
}

// ---------------- launch ----------------
extern "C" void kernel_launch(void* const* d_in, const int* in_sizes, int n_in,
                              void* d_out, int out_size) {
    const float* h   = (const float*)d_in[0];   // [8192,256]
    const float* W1  = (const float*)d_in[1];   // [4,64,256] -> [256,256]
    const float* a1  = (const float*)d_in[2];   // [4,128]
    const float* W2  = (const float*)d_in[3];   // [128,256]
    const float* a2  = (const float*)d_in[4];   // [256]
    const int*  esrc = (const int*)d_in[5];     // [E]
    const int*  edst = (const int*)d_in[6];     // [E]
    float* out = (float*)d_out;

    float *pCs1, *pCs2, *pS1s, *pS1d, *pS2s, *pS2d;
    __half *pWh1h, *pWh2h, *phHi, *phLo, *pxHi, *pxLo, *pw1Hi, *pw1Lo, *pw2Hi, *pw2Lo;
    cudaGetSymbolAddress((void**)&pWh1h, g_Wh1h);
    cudaGetSymbolAddress((void**)&pWh2h, g_Wh2h);
    cudaGetSymbolAddress((void**)&phHi,  g_hHi);
    cudaGetSymbolAddress((void**)&phLo,  g_hLo);
    cudaGetSymbolAddress((void**)&pxHi,  g_xHi);
    cudaGetSymbolAddress((void**)&pxLo,  g_xLo);
    cudaGetSymbolAddress((void**)&pw1Hi, g_w1Hi);
    cudaGetSymbolAddress((void**)&pw1Lo, g_w1Lo);
    cudaGetSymbolAddress((void**)&pw2Hi, g_w2Hi);
    cudaGetSymbolAddress((void**)&pw2Lo, g_w2Lo);
    cudaGetSymbolAddress((void**)&pCs1,  g_colsum1);
    cudaGetSymbolAddress((void**)&pCs2,  g_colsum2);
    cudaGetSymbolAddress((void**)&pS1s,  g_s1src);
    cudaGetSymbolAddress((void**)&pS1d,  g_s1dst);
    cudaGetSymbolAddress((void**)&pS2s,  g_s2src);
    cudaGetSymbolAddress((void**)&pS2d,  g_s2dst);

    const int SMEM_SZ = 65536;
    cudaFuncSetAttribute(k_gemm_mma<64>,  cudaFuncAttributeMaxDynamicSharedMemorySize, SMEM_SZ);
    cudaFuncSetAttribute(k_gemm_mma<128>, cudaFuncAttributeMaxDynamicSharedMemorySize, SMEM_SZ);

    k_zero<<<512, 1024>>>(a1, a2);
    k_cvt<<<2048, 256>>>(h, W1, W2);
    k_mark<<<EDGES / 256, 256>>>(esrc, edst);

    // layer 1
    k_gemm_mma<64><<<dim3(64, 2), 256, SMEM_SZ>>>(phHi, phLo, pw1Hi, pw1Lo,
                                                  pWh1h, a1, pS1s, pS1d, pCs1, 256);
    k_agg1<<<8192, 128>>>();

    // layer 2
    k_gemm_mma<128><<<dim3(64, 1), 256, SMEM_SZ>>>(pxHi, pxLo, pw2Hi, pw2Lo,
                                                   pWh2h, a2, pS2s, pS2d, pCs2, 128);
    k_agg2<<<1024, 256>>>(out);
}

// round 9
// speedup vs baseline: 1.2503x; 1.0497x over previous
#include <cuda_runtime.h>
#include <cuda_fp16.h>
#include <cstdint>

#define NNODES 8192
#define EDGES  262144
#define NHEAD  4
#define NEG_FILL -9.0e15f
#define BCAP 128

// ---------------- scratch (no allocations allowed) ----------------
__device__ __half g_Wh1h[NNODES * 256];
__device__ __half g_Wh2h[NNODES * 128];
__device__ __half g_hHi [NNODES * 256];
__device__ __half g_hLo [NNODES * 256];
__device__ __half g_xHi [NNODES * 256];
__device__ __half g_xLo [NNODES * 256];
__device__ __half g_w1Hi[256 * 256];
__device__ __half g_w1Lo[256 * 256];
__device__ __half g_w2Hi[128 * 256];
__device__ __half g_w2Lo[128 * 256];
__device__ float g_s1src[NHEAD * NNODES];
__device__ float g_s1dst[NHEAD * NNODES];
__device__ float g_s2src[NNODES];
__device__ float g_s2dst[NNODES];
__device__ float g_colsum1[256];
__device__ float g_colsum2[128];
__device__ float g_fill[8];              // [0..3] layer1 heads, [4] layer2
__device__ unsigned g_bitmap[NNODES * NNODES / 32];   // 8 MB dedup bitmap
__device__ int g_deg[NNODES];
__device__ int g_bucket[NNODES * BCAP];  // 4 MB neighbor buckets

__device__ __forceinline__ float lrelu(float x) { return x > 0.f ? x : 0.2f * x; }
__device__ __forceinline__ float elu(float x)   { return x > 0.f ? x : expm1f(x); }

__device__ __forceinline__ uint32_t smem_u32(const void* p) {
    uint32_t a;
    asm("{ .reg .u64 t; cvta.to.shared.u64 t, %1; cvt.u32.u64 %0, t; }" : "=r"(a) : "l"(p));
    return a;
}
__device__ __forceinline__ void ldsm4(uint32_t* r, uint32_t addr) {
    asm volatile("ldmatrix.sync.aligned.m8n8.x4.shared.b16 {%0,%1,%2,%3}, [%4];"
                 : "=r"(r[0]), "=r"(r[1]), "=r"(r[2]), "=r"(r[3]) : "r"(addr));
}
__device__ __forceinline__ void mma16816(float* d, const uint32_t* a, uint32_t b0, uint32_t b1) {
    asm volatile("mma.sync.aligned.m16n8k16.row.col.f32.f16.f16.f32 "
                 "{%0,%1,%2,%3}, {%4,%5,%6,%7}, {%8,%9}, {%0,%1,%2,%3};"
                 : "+f"(d[0]), "+f"(d[1]), "+f"(d[2]), "+f"(d[3])
                 : "r"(a[0]), "r"(a[1]), "r"(a[2]), "r"(a[3]), "r"(b0), "r"(b1));
}
__device__ __forceinline__ uint32_t sw_addr(uint32_t base, int row, int chunk) {
    return base + row * 128 + (((chunk ^ (row & 7)) << 4));
}
__device__ __forceinline__ void cp16(uint32_t saddr, const void* gaddr) {
    asm volatile("cp.async.cg.shared.global [%0], [%1], 16;" :: "r"(saddr), "l"(gaddr));
}

// ---------------- zero scratch + fill constants + fp16 hi/lo cvt ----------------
__device__ __forceinline__ void cvt4(const float* __restrict__ in, int i4,
                                     __half* __restrict__ hi, __half* __restrict__ lo) {
    float4 v = ((const float4*)in)[i4];
    __half2 h0 = __floats2half2_rn(v.x, v.y);
    __half2 h1 = __floats2half2_rn(v.z, v.w);
    float2 f0 = __half22float2(h0), f1 = __half22float2(h1);
    __half2 l0 = __floats2half2_rn(v.x - f0.x, v.y - f0.y);
    __half2 l1 = __floats2half2_rn(v.z - f1.x, v.w - f1.y);
    ((uint2*)hi)[i4] = make_uint2(*(uint32_t*)&h0, *(uint32_t*)&h1);
    ((uint2*)lo)[i4] = make_uint2(*(uint32_t*)&l0, *(uint32_t*)&l1);
}

__global__ void k_zero(const float* __restrict__ h, const float* __restrict__ W1,
                       const float* __restrict__ W2,
                       const float* __restrict__ a1, const float* __restrict__ a2) {
    int idx = blockIdx.x * blockDim.x + threadIdx.x;      // 512 x 1024 = 524288
    ((uint4*)g_bitmap)[idx] = make_uint4(0u, 0u, 0u, 0u);
    cvt4(h, idx, g_hHi, g_hLo);                            // NNODES*256/4 == 524288
    float4 z = make_float4(0.f, 0.f, 0.f, 0.f);
    if (idx < 256 * 256 / 4) cvt4(W1, idx, g_w1Hi, g_w1Lo);
    if (idx < 128 * 256 / 4) cvt4(W2, idx, g_w2Hi, g_w2Lo);
    if (idx < NNODES / 4) ((int4*)g_deg)[idx] = make_int4(0, 0, 0, 0);
    if (idx < 64) ((float4*)g_colsum1)[idx] = z;
    if (idx < 32) ((float4*)g_colsum2)[idx] = z;
    if (idx < NHEAD * NNODES / 4) { ((float4*)g_s1src)[idx] = z; ((float4*)g_s1dst)[idx] = z; }
    if (idx < NNODES / 4) { ((float4*)g_s2src)[idx] = z; ((float4*)g_s2dst)[idx] = z; }
    if (blockIdx.x == 0 && threadIdx.x < 32) {
        int lane = threadIdx.x;
#pragma unroll
        for (int k = 0; k < 4; k++) {
            float s = 0.f;
            for (int d = lane; d < 128; d += 32) s += a1[k * 128 + d];
#pragma unroll
            for (int off = 16; off; off >>= 1) s += __shfl_xor_sync(0xffffffffu, s, off);
            if (lane == 0) g_fill[k] = lrelu(NEG_FILL * s);
        }
        float s = 0.f;
        for (int d = lane; d < 256; d += 32) s += a2[d];
#pragma unroll
        for (int off = 16; off; off >>= 1) s += __shfl_xor_sync(0xffffffffu, s, off);
        if (lane == 0) g_fill[4] = lrelu(NEG_FILL * s);
    }
}

// ---------------- edge dedup + direct bucket CSR ----------------
__global__ void k_mark(const int* __restrict__ src, const int* __restrict__ dst) {
    int e = blockIdx.x * blockDim.x + threadIdx.x;
    if (e >= EDGES) return;
    int s = src[e], d = dst[e];
    unsigned idx = (unsigned)s * NNODES + (unsigned)d;
    unsigned mask = 1u << (idx & 31u);
    unsigned old = atomicOr(&g_bitmap[idx >> 5], mask);
    if (!(old & mask)) {
        int slot = atomicAdd(&g_deg[s], 1);
        g_bucket[s * BCAP + slot] = d;
    }
}

// ---------------- HMMA GEMM, cp.async 2-stage pipeline + fused stats ----------------
template <int HW>
__global__ void __launch_bounds__(256) k_gemm_mma(
    const __half* __restrict__ Ahi, const __half* __restrict__ Alo,
    const __half* __restrict__ Bhi, const __half* __restrict__ Blo,
    __half* __restrict__ Ch, const float* __restrict__ avec,
    float* __restrict__ ssrc, float* __restrict__ sdst,
    float* __restrict__ colsum, int Nn)
{
    extern __shared__ char smem[];
    uint32_t sb = smem_u32(smem);
    const uint32_t STAGE = 65536;
    const uint32_t AHI = 0, ALO = 16384, BHI = 32768, BLO = 49152;
    const int tid = threadIdx.x, lane = tid & 31, wid = tid >> 5;
    const int wm = wid & 3, wn = wid >> 2;          // 4 x 2 warp grid
    const int bm = blockIdx.x * 128, bn = blockIdx.y * 128;

    float acc[2][8][4];
#pragma unroll
    for (int i = 0; i < 2; i++)
#pragma unroll
        for (int j = 0; j < 8; j++)
#pragma unroll
            for (int q = 0; q < 4; q++) acc[i][j][q] = 0.f;

    const int g = lane >> 3, lr = lane & 7;

    // prefetch lambda: chunk kc -> stage st (16 cp.async/thread)
    auto prefetch = [&](int kc, uint32_t st) {
        const __half* srcs[4] = {Ahi, Alo, Bhi, Blo};
        const uint32_t bases[4] = {AHI, ALO, BHI, BLO};
#pragma unroll
        for (int rgn = 0; rgn < 4; rgn++) {
            const __half* src = srcs[rgn];
            const int rowbase = (rgn < 2) ? bm : bn;
            const uint32_t sbase = sb + st + bases[rgn];
#pragma unroll
            for (int q = tid; q < 1024; q += 256) {
                int row = q >> 3, c = q & 7;
                cp16(sbase + row * 128 + (((c ^ (row & 7)) << 4)),
                     src + (size_t)(rowbase + row) * 256 + kc * 64 + c * 8);
            }
        }
    };

    prefetch(0, 0);
    asm volatile("cp.async.commit_group;");

    for (int kc = 0; kc < 4; kc++) {
        const uint32_t cur = (kc & 1) * STAGE;
        if (kc < 3) {
            prefetch(kc + 1, ((kc + 1) & 1) * STAGE);
            asm volatile("cp.async.commit_group;");
            asm volatile("cp.async.wait_group 1;");
        } else {
            asm volatile("cp.async.wait_group 0;");
        }
        __syncthreads();

#pragma unroll
        for (int ks = 0; ks < 4; ks++) {
            const int chunk = ks * 2 + (g >> 1);
            uint32_t ahi[2][4], alo[2][4], bhi[4][4], blo[4][4];
#pragma unroll
            for (int am = 0; am < 2; am++) {
                int row = wm * 32 + am * 16 + (g & 1) * 8 + lr;
                ldsm4(ahi[am], sw_addr(sb + cur + AHI, row, chunk));
                ldsm4(alo[am], sw_addr(sb + cur + ALO, row, chunk));
            }
#pragma unroll
            for (int bp = 0; bp < 4; bp++) {
                int row = wn * 64 + bp * 16 + (g & 1) * 8 + lr;
                ldsm4(bhi[bp], sw_addr(sb + cur + BHI, row, chunk));
                ldsm4(blo[bp], sw_addr(sb + cur + BLO, row, chunk));
            }
#pragma unroll
            for (int am = 0; am < 2; am++)
#pragma unroll
                for (int bp = 0; bp < 4; bp++) {
                    float* c0 = acc[am][bp * 2];
                    float* c1 = acc[am][bp * 2 + 1];
                    mma16816(c0, ahi[am], bhi[bp][0], bhi[bp][2]);
                    mma16816(c1, ahi[am], bhi[bp][1], bhi[bp][3]);
                    mma16816(c0, ahi[am], blo[bp][0], blo[bp][2]);
                    mma16816(c1, ahi[am], blo[bp][1], blo[bp][3]);
                    mma16816(c0, alo[am], bhi[bp][0], bhi[bp][2]);
                    mma16816(c1, alo[am], bhi[bp][1], bhi[bp][3]);
                }
        }
        __syncthreads();
    }

    // ---- epilogue: fp16 store + fused stats ----
    const int head = (bn + wn * 64) / HW;
    const int cbase = ((wn * 64) % HW) + (lane & 3) * 2;
    float aS[16], aD[16];
#pragma unroll
    for (int j = 0; j < 8; j++)
#pragma unroll
        for (int p = 0; p < 2; p++) {
            int cc = cbase + j * 8 + p;
            aS[j * 2 + p] = __ldg(&avec[head * 2 * HW + cc]);
            aD[j * 2 + p] = __ldg(&avec[head * 2 * HW + HW + cc]);
        }
    float ps[4] = {0.f, 0.f, 0.f, 0.f}, pd[4] = {0.f, 0.f, 0.f, 0.f}, cs[16];
#pragma unroll
    for (int c = 0; c < 16; c++) cs[c] = 0.f;

#pragma unroll
    for (int am = 0; am < 2; am++) {
        int r0 = bm + wm * 32 + am * 16 + (lane >> 2);
        int c0 = bn + wn * 64 + (lane & 3) * 2;
#pragma unroll
        for (int j = 0; j < 8; j++) {
            __half2 h0 = __floats2half2_rn(acc[am][j][0], acc[am][j][1]);
            __half2 h1 = __floats2half2_rn(acc[am][j][2], acc[am][j][3]);
            *(__half2*)&Ch[(size_t)r0 * Nn + c0 + j * 8]       = h0;
            *(__half2*)&Ch[(size_t)(r0 + 8) * Nn + c0 + j * 8] = h1;
#pragma unroll
            for (int q = 0; q < 4; q++) {
                float v = acc[am][j][q];
                int ridx = am * 2 + (q >> 1);
                int cidx = j * 2 + (q & 1);
                ps[ridx] = fmaf(v, aS[cidx], ps[ridx]);
                pd[ridx] = fmaf(v, aD[cidx], pd[ridx]);
                cs[cidx] += v;
            }
        }
    }
#pragma unroll
    for (int off = 1; off <= 2; off <<= 1)
#pragma unroll
        for (int r = 0; r < 4; r++) {
            ps[r] += __shfl_xor_sync(0xffffffffu, ps[r], off);
            pd[r] += __shfl_xor_sync(0xffffffffu, pd[r], off);
        }
    if ((lane & 3) == 0) {
#pragma unroll
        for (int r = 0; r < 4; r++) {
            int row = bm + wm * 32 + (r >> 1) * 16 + (lane >> 2) + (r & 1) * 8;
            atomicAdd(&ssrc[(size_t)head * NNODES + row], ps[r]);
            atomicAdd(&sdst[(size_t)head * NNODES + row], pd[r]);
        }
    }
#pragma unroll
    for (int off = 4; off <= 16; off <<= 1)
#pragma unroll
        for (int c = 0; c < 16; c++) cs[c] += __shfl_xor_sync(0xffffffffu, cs[c], off);
    if (lane < 4) {
#pragma unroll
        for (int j = 0; j < 8; j++)
#pragma unroll
            for (int p = 0; p < 2; p++) {
                int col = bn + wn * 64 + lane * 2 + j * 8 + p;
                atomicAdd(&colsum[col], cs[j * 2 + p]);
            }
    }
}

// ---------------- layer-1 aggregation: block per node, warp per head ----------------
__global__ void k_agg1() {
    int i = blockIdx.x;
    int k = threadIdx.x >> 5, lane = threadIdx.x & 31;
    int deg = g_deg[i];
    const int* bkt = &g_bucket[i * BCAP];
    float c0 = g_colsum1[k * 64 + 2 * lane], c1 = g_colsum1[k * 64 + 2 * lane + 1];
    float o0, o1;
    if (deg == 0) {
        o0 = c0 * (1.f / NNODES);
        o1 = c1 * (1.f / NNODES);
    } else {
        float ssrc = g_s1src[k * NNODES + i];
        float fill = g_fill[k];
        float m = fmaxf(fill, 0.f);
        float acc0 = 0.f, acc1 = 0.f, an0 = 0.f, an1 = 0.f, ws = 0.f;
        for (int t = 0; t < deg; t++) {
            int j = bkt[t];
            float e = lrelu(ssrc + g_s1dst[k * NNODES + j]);
            float wgt = __expf(e - m);
            ws += wgt;
            __half2 v = *(const __half2*)&g_Wh1h[(size_t)j * 256 + k * 64 + 2 * lane];
            float2 vf = __half22float2(v);
            acc0 = fmaf(wgt, vf.x, acc0); acc1 = fmaf(wgt, vf.y, acc1);
            an0 += vf.x; an1 += vf.y;
        }
        float wf = __expf(fill - m);
        float denom = ws + (float)(NNODES - deg) * wf;
        o0 = (acc0 + wf * (c0 - an0)) / denom;
        o1 = (acc1 + wf * (c1 - an1)) / denom;
    }
    o0 = elu(o0); o1 = elu(o1);
    __half2 hi = __floats2half2_rn(o0, o1);
    float2 hf = __half22float2(hi);
    __half2 lo = __floats2half2_rn(o0 - hf.x, o1 - hf.y);
    size_t off_ = (size_t)i * 256 + k * 64 + 2 * lane;
    *(__half2*)&g_xHi[off_] = hi;
    *(__half2*)&g_xLo[off_] = lo;
}

// ---------------- layer-2 aggregation: warp per node ----------------
__global__ void k_agg2(float* __restrict__ out) {
    int i = (blockIdx.x * blockDim.x + threadIdx.x) >> 5;
    int lane = threadIdx.x & 31;
    if (i >= NNODES) return;
    int deg = g_deg[i];
    const int* bkt = &g_bucket[i * BCAP];
    float o[4];
    if (deg == 0) {
#pragma unroll
        for (int r = 0; r < 4; r++) o[r] = g_colsum2[4 * lane + r] * (1.f / NNODES);
    } else {
        float ssrc = g_s2src[i];
        float fill = g_fill[4];
        float m = fmaxf(fill, 0.f);
        float acc[4] = {0.f, 0.f, 0.f, 0.f}, an[4] = {0.f, 0.f, 0.f, 0.f}, ws = 0.f;
        for (int t = 0; t < deg; t++) {
            int j = bkt[t];
            float e = lrelu(ssrc + g_s2dst[j]);
            float wgt = __expf(e - m);
            ws += wgt;
            uint2 u = *(const uint2*)&g_Wh2h[(size_t)j * 128 + 4 * lane];
            float2 va = __half22float2(*(__half2*)&u.x);
            float2 vb = __half22float2(*(__half2*)&u.y);
            acc[0] = fmaf(wgt, va.x, acc[0]); an[0] += va.x;
            acc[1] = fmaf(wgt, va.y, acc[1]); an[1] += va.y;
            acc[2] = fmaf(wgt, vb.x, acc[2]); an[2] += vb.x;
            acc[3] = fmaf(wgt, vb.y, acc[3]); an[3] += vb.y;
        }
        float wf = __expf(fill - m);
        float denom = ws + (float)(NNODES - deg) * wf;
#pragma unroll
        for (int r = 0; r < 4; r++)
            o[r] = (acc[r] + wf * (g_colsum2[4 * lane + r] - an[r])) / denom;
    }
#pragma unroll
    for (int r = 0; r < 4; r++)
        out[(size_t)i * 128 + 4 * lane + r] = elu(elu(o[r]));
}

// ---------------- launch ----------------
extern "C" void kernel_launch(void* const* d_in, const int* in_sizes, int n_in,
                              void* d_out, int out_size) {
    const float* h   = (const float*)d_in[0];   // [8192,256]
    const float* W1  = (const float*)d_in[1];   // [4,64,256] -> [256,256]
    const float* a1  = (const float*)d_in[2];   // [4,128]
    const float* W2  = (const float*)d_in[3];   // [128,256]
    const float* a2  = (const float*)d_in[4];   // [256]
    const int*  esrc = (const int*)d_in[5];     // [E]
    const int*  edst = (const int*)d_in[6];     // [E]
    float* out = (float*)d_out;

    float *pCs1, *pCs2, *pS1s, *pS1d, *pS2s, *pS2d;
    __half *pWh1h, *pWh2h, *phHi, *phLo, *pxHi, *pxLo, *pw1Hi, *pw1Lo, *pw2Hi, *pw2Lo;
    cudaGetSymbolAddress((void**)&pWh1h, g_Wh1h);
    cudaGetSymbolAddress((void**)&pWh2h, g_Wh2h);
    cudaGetSymbolAddress((void**)&phHi,  g_hHi);
    cudaGetSymbolAddress((void**)&phLo,  g_hLo);
    cudaGetSymbolAddress((void**)&pxHi,  g_xHi);
    cudaGetSymbolAddress((void**)&pxLo,  g_xLo);
    cudaGetSymbolAddress((void**)&pw1Hi, g_w1Hi);
    cudaGetSymbolAddress((void**)&pw1Lo, g_w1Lo);
    cudaGetSymbolAddress((void**)&pw2Hi, g_w2Hi);
    cudaGetSymbolAddress((void**)&pw2Lo, g_w2Lo);
    cudaGetSymbolAddress((void**)&pCs1,  g_colsum1);
    cudaGetSymbolAddress((void**)&pCs2,  g_colsum2);
    cudaGetSymbolAddress((void**)&pS1s,  g_s1src);
    cudaGetSymbolAddress((void**)&pS1d,  g_s1dst);
    cudaGetSymbolAddress((void**)&pS2s,  g_s2src);
    cudaGetSymbolAddress((void**)&pS2d,  g_s2dst);

    const int SMEM_SZ = 131072;   // 2-stage pipeline
    cudaFuncSetAttribute(k_gemm_mma<64>,  cudaFuncAttributeMaxDynamicSharedMemorySize, SMEM_SZ);
    cudaFuncSetAttribute(k_gemm_mma<128>, cudaFuncAttributeMaxDynamicSharedMemorySize, SMEM_SZ);

    k_zero<<<512, 1024>>>(h, W1, W2, a1, a2);
    k_mark<<<EDGES / 256, 256>>>(esrc, edst);

    // layer 1
    k_gemm_mma<64><<<dim3(64, 2), 256, SMEM_SZ>>>(phHi, phLo, pw1Hi, pw1Lo,
                                                  pWh1h, a1, pS1s, pS1d, pCs1, 256);
    k_agg1<<<8192, 128>>>();

    // layer 2
    k_gemm_mma<128><<<dim3(64, 1), 256, SMEM_SZ>>>(pxHi, pxLo, pw2Hi, pw2Lo,
                                                   pWh2h, a2, pS2s, pS2d, pCs2, 128);
    k_agg2<<<1024, 256>>>(out);
}

// round 10
// speedup vs baseline: 1.3339x; 1.0669x over previous
#include <cuda_runtime.h>
#include <cuda_fp16.h>
#include <cstdint>

#define NNODES 8192
#define EDGES  262144
#define NHEAD  4
#define NEG_FILL -9.0e15f
#define BCAP 128

// ---------------- scratch (no allocations allowed) ----------------
__device__ __half g_Wh1h[NNODES * 256];
__device__ __half g_Wh2h[NNODES * 128];
__device__ __half g_hHi [NNODES * 256];
__device__ __half g_hLo [NNODES * 256];
__device__ __half g_xHi [NNODES * 256];
__device__ __half g_xLo [NNODES * 256];
__device__ __half g_w1Hi[256 * 256];
__device__ __half g_w1Lo[256 * 256];
__device__ __half g_w2Hi[128 * 256];
__device__ __half g_w2Lo[128 * 256];
__device__ float g_s1src[NHEAD * NNODES];
__device__ float g_s1dst[NHEAD * NNODES];
__device__ float g_s2src[NNODES];
__device__ float g_s2dst[NNODES];
__device__ float g_colsum1[256];
__device__ float g_colsum2[128];
__device__ float g_fill[8];              // [0..3] layer1 heads, [4] layer2
__device__ unsigned g_bitmap[NNODES * NNODES / 32];   // 8 MB dedup bitmap
__device__ int g_deg[NNODES];
__device__ int g_bucket[NNODES * BCAP];  // 4 MB neighbor buckets

__device__ __forceinline__ float lrelu(float x) { return x > 0.f ? x : 0.2f * x; }
__device__ __forceinline__ float elu(float x)   { return x > 0.f ? x : expm1f(x); }

__device__ __forceinline__ uint32_t smem_u32(const void* p) {
    uint32_t a;
    asm("{ .reg .u64 t; cvta.to.shared.u64 t, %1; cvt.u32.u64 %0, t; }" : "=r"(a) : "l"(p));
    return a;
}
__device__ __forceinline__ void ldsm4(uint32_t* r, uint32_t addr) {
    asm volatile("ldmatrix.sync.aligned.m8n8.x4.shared.b16 {%0,%1,%2,%3}, [%4];"
                 : "=r"(r[0]), "=r"(r[1]), "=r"(r[2]), "=r"(r[3]) : "r"(addr));
}
__device__ __forceinline__ void mma16816(float* d, const uint32_t* a, uint32_t b0, uint32_t b1) {
    asm volatile("mma.sync.aligned.m16n8k16.row.col.f32.f16.f16.f32 "
                 "{%0,%1,%2,%3}, {%4,%5,%6,%7}, {%8,%9}, {%0,%1,%2,%3};"
                 : "+f"(d[0]), "+f"(d[1]), "+f"(d[2]), "+f"(d[3])
                 : "r"(a[0]), "r"(a[1]), "r"(a[2]), "r"(a[3]), "r"(b0), "r"(b1));
}
__device__ __forceinline__ uint32_t sw_addr(uint32_t base, int row, int chunk) {
    return base + row * 128 + (((chunk ^ (row & 7)) << 4));
}
__device__ __forceinline__ void cp16(uint32_t saddr, const void* gaddr) {
    asm volatile("cp.async.cg.shared.global [%0], [%1], 16;" :: "r"(saddr), "l"(gaddr));
}

// ---------------- zero scratch + fill constants + fp16 hi/lo cvt ----------------
__device__ __forceinline__ void cvt4(const float* __restrict__ in, int i4,
                                     __half* __restrict__ hi, __half* __restrict__ lo) {
    float4 v = ((const float4*)in)[i4];
    __half2 h0 = __floats2half2_rn(v.x, v.y);
    __half2 h1 = __floats2half2_rn(v.z, v.w);
    float2 f0 = __half22float2(h0), f1 = __half22float2(h1);
    __half2 l0 = __floats2half2_rn(v.x - f0.x, v.y - f0.y);
    __half2 l1 = __floats2half2_rn(v.z - f1.x, v.w - f1.y);
    ((uint2*)hi)[i4] = make_uint2(*(uint32_t*)&h0, *(uint32_t*)&h1);
    ((uint2*)lo)[i4] = make_uint2(*(uint32_t*)&l0, *(uint32_t*)&l1);
}

__global__ void k_zero(const float* __restrict__ h, const float* __restrict__ W1,
                       const float* __restrict__ W2,
                       const float* __restrict__ a1, const float* __restrict__ a2) {
    int idx = blockIdx.x * blockDim.x + threadIdx.x;      // 512 x 1024 = 524288
    ((uint4*)g_bitmap)[idx] = make_uint4(0u, 0u, 0u, 0u);
    cvt4(h, idx, g_hHi, g_hLo);                            // NNODES*256/4 == 524288
    float4 z = make_float4(0.f, 0.f, 0.f, 0.f);
    if (idx < 256 * 256 / 4) cvt4(W1, idx, g_w1Hi, g_w1Lo);
    if (idx < 128 * 256 / 4) cvt4(W2, idx, g_w2Hi, g_w2Lo);
    if (idx < NNODES / 4) ((int4*)g_deg)[idx] = make_int4(0, 0, 0, 0);
    if (idx < 64) ((float4*)g_colsum1)[idx] = z;
    if (idx < 32) ((float4*)g_colsum2)[idx] = z;
    if (idx < NHEAD * NNODES / 4) { ((float4*)g_s1src)[idx] = z; ((float4*)g_s1dst)[idx] = z; }
    if (idx < NNODES / 4) { ((float4*)g_s2src)[idx] = z; ((float4*)g_s2dst)[idx] = z; }
    if (blockIdx.x == 0 && threadIdx.x < 32) {
        int lane = threadIdx.x;
#pragma unroll
        for (int k = 0; k < 4; k++) {
            float s = 0.f;
            for (int d = lane; d < 128; d += 32) s += a1[k * 128 + d];
#pragma unroll
            for (int off = 16; off; off >>= 1) s += __shfl_xor_sync(0xffffffffu, s, off);
            if (lane == 0) g_fill[k] = lrelu(NEG_FILL * s);
        }
        float s = 0.f;
        for (int d = lane; d < 256; d += 32) s += a2[d];
#pragma unroll
        for (int off = 16; off; off >>= 1) s += __shfl_xor_sync(0xffffffffu, s, off);
        if (lane == 0) g_fill[4] = lrelu(NEG_FILL * s);
    }
}

// ---------------- edge dedup + direct bucket CSR ----------------
__global__ void k_mark(const int* __restrict__ src, const int* __restrict__ dst) {
    int e = blockIdx.x * blockDim.x + threadIdx.x;
    if (e >= EDGES) return;
    int s = src[e], d = dst[e];
    unsigned idx = (unsigned)s * NNODES + (unsigned)d;
    unsigned mask = 1u << (idx & 31u);
    unsigned old = atomicOr(&g_bitmap[idx >> 5], mask);
    if (!(old & mask)) {
        int slot = atomicAdd(&g_deg[s], 1);
        g_bucket[s * BCAP + slot] = d;
    }
}

// ---------------- HMMA GEMM, cp.async 2-stage pipeline + fused stats ----------------
template <int HW>
__global__ void __launch_bounds__(256) k_gemm_mma(
    const __half* __restrict__ Ahi, const __half* __restrict__ Alo,
    const __half* __restrict__ Bhi, const __half* __restrict__ Blo,
    __half* __restrict__ Ch, const float* __restrict__ avec,
    float* __restrict__ ssrc, float* __restrict__ sdst,
    float* __restrict__ colsum, int Nn)
{
    extern __shared__ char smem[];
    uint32_t sb = smem_u32(smem);
    const uint32_t STAGE = 65536;
    const uint32_t AHI = 0, ALO = 16384, BHI = 32768, BLO = 49152;
    const int tid = threadIdx.x, lane = tid & 31, wid = tid >> 5;
    const int wm = wid & 3, wn = wid >> 2;          // 4 x 2 warp grid
    const int bm = blockIdx.x * 128, bn = blockIdx.y * 128;

    float acc[2][8][4];
#pragma unroll
    for (int i = 0; i < 2; i++)
#pragma unroll
        for (int j = 0; j < 8; j++)
#pragma unroll
            for (int q = 0; q < 4; q++) acc[i][j][q] = 0.f;

    const int g = lane >> 3, lr = lane & 7;

    auto prefetch = [&](int kc, uint32_t st) {
        const __half* srcs[4] = {Ahi, Alo, Bhi, Blo};
        const uint32_t bases[4] = {AHI, ALO, BHI, BLO};
#pragma unroll
        for (int rgn = 0; rgn < 4; rgn++) {
            const __half* src = srcs[rgn];
            const int rowbase = (rgn < 2) ? bm : bn;
            const uint32_t sbase = sb + st + bases[rgn];
#pragma unroll
            for (int q = tid; q < 1024; q += 256) {
                int row = q >> 3, c = q & 7;
                cp16(sbase + row * 128 + (((c ^ (row & 7)) << 4)),
                     src + (size_t)(rowbase + row) * 256 + kc * 64 + c * 8);
            }
        }
    };

    prefetch(0, 0);
    asm volatile("cp.async.commit_group;");

    for (int kc = 0; kc < 4; kc++) {
        const uint32_t cur = (kc & 1) * STAGE;
        if (kc < 3) {
            prefetch(kc + 1, ((kc + 1) & 1) * STAGE);
            asm volatile("cp.async.commit_group;");
            asm volatile("cp.async.wait_group 1;");
        } else {
            asm volatile("cp.async.wait_group 0;");
        }
        __syncthreads();

#pragma unroll
        for (int ks = 0; ks < 4; ks++) {
            const int chunk = ks * 2 + (g >> 1);
            uint32_t ahi[2][4], alo[2][4], bhi[4][4], blo[4][4];
#pragma unroll
            for (int am = 0; am < 2; am++) {
                int row = wm * 32 + am * 16 + (g & 1) * 8 + lr;
                ldsm4(ahi[am], sw_addr(sb + cur + AHI, row, chunk));
                ldsm4(alo[am], sw_addr(sb + cur + ALO, row, chunk));
            }
#pragma unroll
            for (int bp = 0; bp < 4; bp++) {
                int row = wn * 64 + bp * 16 + (g & 1) * 8 + lr;
                ldsm4(bhi[bp], sw_addr(sb + cur + BHI, row, chunk));
                ldsm4(blo[bp], sw_addr(sb + cur + BLO, row, chunk));
            }
#pragma unroll
            for (int am = 0; am < 2; am++)
#pragma unroll
                for (int bp = 0; bp < 4; bp++) {
                    float* c0 = acc[am][bp * 2];
                    float* c1 = acc[am][bp * 2 + 1];
                    mma16816(c0, ahi[am], bhi[bp][0], bhi[bp][2]);
                    mma16816(c1, ahi[am], bhi[bp][1], bhi[bp][3]);
                    mma16816(c0, ahi[am], blo[bp][0], blo[bp][2]);
                    mma16816(c1, ahi[am], blo[bp][1], blo[bp][3]);
                    mma16816(c0, alo[am], bhi[bp][0], bhi[bp][2]);
                    mma16816(c1, alo[am], bhi[bp][1], bhi[bp][3]);
                }
        }
        __syncthreads();
    }

    // ---- epilogue: fp16 store + fused stats ----
    const int head = (bn + wn * 64) / HW;
    const int cbase = ((wn * 64) % HW) + (lane & 3) * 2;
    float aS[16], aD[16];
#pragma unroll
    for (int j = 0; j < 8; j++)
#pragma unroll
        for (int p = 0; p < 2; p++) {
            int cc = cbase + j * 8 + p;
            aS[j * 2 + p] = __ldg(&avec[head * 2 * HW + cc]);
            aD[j * 2 + p] = __ldg(&avec[head * 2 * HW + HW + cc]);
        }
    float ps[4] = {0.f, 0.f, 0.f, 0.f}, pd[4] = {0.f, 0.f, 0.f, 0.f}, cs[16];
#pragma unroll
    for (int c = 0; c < 16; c++) cs[c] = 0.f;

#pragma unroll
    for (int am = 0; am < 2; am++) {
        int r0 = bm + wm * 32 + am * 16 + (lane >> 2);
        int c0 = bn + wn * 64 + (lane & 3) * 2;
#pragma unroll
        for (int j = 0; j < 8; j++) {
            __half2 h0 = __floats2half2_rn(acc[am][j][0], acc[am][j][1]);
            __half2 h1 = __floats2half2_rn(acc[am][j][2], acc[am][j][3]);
            *(__half2*)&Ch[(size_t)r0 * Nn + c0 + j * 8]       = h0;
            *(__half2*)&Ch[(size_t)(r0 + 8) * Nn + c0 + j * 8] = h1;
#pragma unroll
            for (int q = 0; q < 4; q++) {
                float v = acc[am][j][q];
                int ridx = am * 2 + (q >> 1);
                int cidx = j * 2 + (q & 1);
                ps[ridx] = fmaf(v, aS[cidx], ps[ridx]);
                pd[ridx] = fmaf(v, aD[cidx], pd[ridx]);
                cs[cidx] += v;
            }
        }
    }
#pragma unroll
    for (int off = 1; off <= 2; off <<= 1)
#pragma unroll
        for (int r = 0; r < 4; r++) {
            ps[r] += __shfl_xor_sync(0xffffffffu, ps[r], off);
            pd[r] += __shfl_xor_sync(0xffffffffu, pd[r], off);
        }
    if ((lane & 3) == 0) {
#pragma unroll
        for (int r = 0; r < 4; r++) {
            int row = bm + wm * 32 + (r >> 1) * 16 + (lane >> 2) + (r & 1) * 8;
            atomicAdd(&ssrc[(size_t)head * NNODES + row], ps[r]);
            atomicAdd(&sdst[(size_t)head * NNODES + row], pd[r]);
        }
    }
#pragma unroll
    for (int off = 4; off <= 16; off <<= 1)
#pragma unroll
        for (int c = 0; c < 16; c++) cs[c] += __shfl_xor_sync(0xffffffffu, cs[c], off);
    if (lane < 4) {
#pragma unroll
        for (int j = 0; j < 8; j++)
#pragma unroll
            for (int p = 0; p < 2; p++) {
                int col = bn + wn * 64 + lane * 2 + j * 8 + p;
                atomicAdd(&colsum[col], cs[j * 2 + p]);
            }
    }
}

// ---------------- layer-1 aggregation: block per node, warp per head ----------------
// Parallel-weight restructure: lane t computes weight of edge t (w - wf folded),
// then shfl-broadcast loop accumulates 2 dims per lane.
__global__ void k_agg1() {
    int i = blockIdx.x;
    int k = threadIdx.x >> 5, lane = threadIdx.x & 31;
    int deg = g_deg[i];
    const int* bkt = &g_bucket[i * BCAP];
    float c0 = g_colsum1[k * 64 + 2 * lane], c1 = g_colsum1[k * 64 + 2 * lane + 1];
    float o0, o1;
    if (deg == 0) {
        o0 = c0 * (1.f / NNODES);
        o1 = c1 * (1.f / NNODES);
    } else {
        const float ssrc = g_s1src[k * NNODES + i];
        const float fill = g_fill[k];
        const float m = fmaxf(fill, 0.f);
        const float wf = __expf(fill - m);
        const float* sdst = &g_s1dst[k * NNODES];
        const __half* wh = &g_Wh1h[k * 64 + 2 * lane];
        float acc0 = 0.f, acc1 = 0.f, wsum = 0.f;
        for (int base = 0; base < deg; base += 32) {
            const int cnt = min(32, deg - base);
            int j = 0; float w = 0.f;
            if (lane < cnt) {
                j = bkt[base + lane];
                w = __expf(lrelu(ssrc + sdst[j]) - m) - wf;
            }
            float wl = w;
#pragma unroll
            for (int off = 16; off; off >>= 1) wl += __shfl_xor_sync(0xffffffffu, wl, off);
            wsum += wl;
            const int cnt4 = (cnt + 3) & ~3;
            for (int t = 0; t < cnt4; t += 4) {
#pragma unroll
                for (int u = 0; u < 4; u++) {
                    float wt = __shfl_sync(0xffffffffu, w, t + u);
                    int jt = __shfl_sync(0xffffffffu, j, t + u);
                    float2 vf = __half22float2(*(const __half2*)&wh[(size_t)jt * 256]);
                    acc0 = fmaf(wt, vf.x, acc0);
                    acc1 = fmaf(wt, vf.y, acc1);
                }
            }
        }
        float denom = wsum + (float)NNODES * wf;
        o0 = (acc0 + wf * c0) / denom;
        o1 = (acc1 + wf * c1) / denom;
    }
    o0 = elu(o0); o1 = elu(o1);
    __half2 hi = __floats2half2_rn(o0, o1);
    float2 hf = __half22float2(hi);
    __half2 lo = __floats2half2_rn(o0 - hf.x, o1 - hf.y);
    size_t off_ = (size_t)i * 256 + k * 64 + 2 * lane;
    *(__half2*)&g_xHi[off_] = hi;
    *(__half2*)&g_xLo[off_] = lo;
}

// ---------------- layer-2 aggregation: warp per node ----------------
__global__ void k_agg2(float* __restrict__ out) {
    int i = (blockIdx.x * blockDim.x + threadIdx.x) >> 5;
    int lane = threadIdx.x & 31;
    if (i >= NNODES) return;
    int deg = g_deg[i];
    const int* bkt = &g_bucket[i * BCAP];
    float o[4];
    if (deg == 0) {
#pragma unroll
        for (int r = 0; r < 4; r++) o[r] = g_colsum2[4 * lane + r] * (1.f / NNODES);
    } else {
        const float ssrc = g_s2src[i];
        const float fill = g_fill[4];
        const float m = fmaxf(fill, 0.f);
        const float wf = __expf(fill - m);
        const __half* wh = &g_Wh2h[4 * lane];
        float acc[4] = {0.f, 0.f, 0.f, 0.f}, wsum = 0.f;
        for (int base = 0; base < deg; base += 32) {
            const int cnt = min(32, deg - base);
            int j = 0; float w = 0.f;
            if (lane < cnt) {
                j = bkt[base + lane];
                w = __expf(lrelu(ssrc + g_s2dst[j]) - m) - wf;
            }
            float wl = w;
#pragma unroll
            for (int off = 16; off; off >>= 1) wl += __shfl_xor_sync(0xffffffffu, wl, off);
            wsum += wl;
            const int cnt4 = (cnt + 3) & ~3;
            for (int t = 0; t < cnt4; t += 4) {
#pragma unroll
                for (int u = 0; u < 4; u++) {
                    float wt = __shfl_sync(0xffffffffu, w, t + u);
                    int jt = __shfl_sync(0xffffffffu, j, t + u);
                    uint2 uv = *(const uint2*)&wh[(size_t)jt * 128];
                    float2 va = __half22float2(*(__half2*)&uv.x);
                    float2 vb = __half22float2(*(__half2*)&uv.y);
                    acc[0] = fmaf(wt, va.x, acc[0]);
                    acc[1] = fmaf(wt, va.y, acc[1]);
                    acc[2] = fmaf(wt, vb.x, acc[2]);
                    acc[3] = fmaf(wt, vb.y, acc[3]);
                }
            }
        }
        float denom = wsum + (float)NNODES * wf;
#pragma unroll
        for (int r = 0; r < 4; r++)
            o[r] = (acc[r] + wf * g_colsum2[4 * lane + r]) / denom;
    }
#pragma unroll
    for (int r = 0; r < 4; r++)
        out[(size_t)i * 128 + 4 * lane + r] = elu(elu(o[r]));
}

// ---------------- launch ----------------
extern "C" void kernel_launch(void* const* d_in, const int* in_sizes, int n_in,
                              void* d_out, int out_size) {
    const float* h   = (const float*)d_in[0];   // [8192,256]
    const float* W1  = (const float*)d_in[1];   // [4,64,256] -> [256,256]
    const float* a1  = (const float*)d_in[2];   // [4,128]
    const float* W2  = (const float*)d_in[3];   // [128,256]
    const float* a2  = (const float*)d_in[4];   // [256]
    const int*  esrc = (const int*)d_in[5];     // [E]
    const int*  edst = (const int*)d_in[6];     // [E]
    float* out = (float*)d_out;

    float *pCs1, *pCs2, *pS1s, *pS1d, *pS2s, *pS2d;
    __half *pWh1h, *pWh2h, *phHi, *phLo, *pxHi, *pxLo, *pw1Hi, *pw1Lo, *pw2Hi, *pw2Lo;
    cudaGetSymbolAddress((void**)&pWh1h, g_Wh1h);
    cudaGetSymbolAddress((void**)&pWh2h, g_Wh2h);
    cudaGetSymbolAddress((void**)&phHi,  g_hHi);
    cudaGetSymbolAddress((void**)&phLo,  g_hLo);
    cudaGetSymbolAddress((void**)&pxHi,  g_xHi);
    cudaGetSymbolAddress((void**)&pxLo,  g_xLo);
    cudaGetSymbolAddress((void**)&pw1Hi, g_w1Hi);
    cudaGetSymbolAddress((void**)&pw1Lo, g_w1Lo);
    cudaGetSymbolAddress((void**)&pw2Hi, g_w2Hi);
    cudaGetSymbolAddress((void**)&pw2Lo, g_w2Lo);
    cudaGetSymbolAddress((void**)&pCs1,  g_colsum1);
    cudaGetSymbolAddress((void**)&pCs2,  g_colsum2);
    cudaGetSymbolAddress((void**)&pS1s,  g_s1src);
    cudaGetSymbolAddress((void**)&pS1d,  g_s1dst);
    cudaGetSymbolAddress((void**)&pS2s,  g_s2src);
    cudaGetSymbolAddress((void**)&pS2d,  g_s2dst);

    const int SMEM_SZ = 131072;   // 2-stage pipeline
    cudaFuncSetAttribute(k_gemm_mma<64>,  cudaFuncAttributeMaxDynamicSharedMemorySize, SMEM_SZ);
    cudaFuncSetAttribute(k_gemm_mma<128>, cudaFuncAttributeMaxDynamicSharedMemorySize, SMEM_SZ);

    k_zero<<<512, 1024>>>(h, W1, W2, a1, a2);
    k_mark<<<EDGES / 256, 256>>>(esrc, edst);

    // layer 1
    k_gemm_mma<64><<<dim3(64, 2), 256, SMEM_SZ>>>(phHi, phLo, pw1Hi, pw1Lo,
                                                  pWh1h, a1, pS1s, pS1d, pCs1, 256);
    k_agg1<<<8192, 128>>>();

    // layer 2
    k_gemm_mma<128><<<dim3(64, 1), 256, SMEM_SZ>>>(pxHi, pxLo, pw2Hi, pw2Lo,
                                                   pWh2h, a2, pS2s, pS2d, pCs2, 128);
    k_agg2<<<1024, 256>>>(out);
}

// round 13
// speedup vs baseline: 1.4389x; 1.0787x over previous
#include <cuda_runtime.h>
#include <cuda_fp16.h>
#include <cstdint>

#define NNODES 8192
#define EDGES  262144
#define NHEAD  4
#define NEG_FILL -9.0e15f
#define BCAP 128

// ---------------- scratch (no allocations allowed) ----------------
__device__ __half g_Wh1h[NNODES * 256];
__device__ __half g_Wh2h[NNODES * 128];
__device__ __half g_hHi [NNODES * 256];
__device__ __half g_hLo [NNODES * 256];
__device__ __half g_xHi [NNODES * 256];
__device__ __half g_xLo [NNODES * 256];
__device__ __half g_w1Hi[256 * 256];
__device__ __half g_w1Lo[256 * 256];
__device__ __half g_w2Hi[128 * 256];
__device__ __half g_w2Lo[128 * 256];
__device__ float g_s1src[NHEAD * NNODES];
__device__ float g_s1dst[NHEAD * NNODES];
__device__ float g_s2src[NNODES];
__device__ float g_s2dst[NNODES];
__device__ float g_colsum1[256];
__device__ float g_colsum2[128];
__device__ float g_fill[8];              // [0..3] layer1 heads, [4] layer2
__device__ unsigned g_bitmap[NNODES * NNODES / 32];   // 8 MB dedup bitmap
__device__ int g_deg[NNODES];
__device__ int g_bucket[NNODES * BCAP];  // 4 MB neighbor buckets

__device__ __forceinline__ float lrelu(float x) { return x > 0.f ? x : 0.2f * x; }
__device__ __forceinline__ float elu(float x)   { return x > 0.f ? x : expm1f(x); }

__device__ __forceinline__ uint32_t smem_u32(const void* p) {
    uint32_t a;
    asm("{ .reg .u64 t; cvta.to.shared.u64 t, %1; cvt.u32.u64 %0, t; }" : "=r"(a) : "l"(p));
    return a;
}
__device__ __forceinline__ void ldsm4(uint32_t* r, uint32_t addr) {
    asm volatile("ldmatrix.sync.aligned.m8n8.x4.shared.b16 {%0,%1,%2,%3}, [%4];"
                 : "=r"(r[0]), "=r"(r[1]), "=r"(r[2]), "=r"(r[3]) : "r"(addr));
}
__device__ __forceinline__ void mma16816(float* d, const uint32_t* a, uint32_t b0, uint32_t b1) {
    asm volatile("mma.sync.aligned.m16n8k16.row.col.f32.f16.f16.f32 "
                 "{%0,%1,%2,%3}, {%4,%5,%6,%7}, {%8,%9}, {%0,%1,%2,%3};"
                 : "+f"(d[0]), "+f"(d[1]), "+f"(d[2]), "+f"(d[3])
                 : "r"(a[0]), "r"(a[1]), "r"(a[2]), "r"(a[3]), "r"(b0), "r"(b1));
}
__device__ __forceinline__ uint32_t sw_addr(uint32_t base, int row, int chunk) {
    return base + row * 128 + (((chunk ^ (row & 7)) << 4));
}
__device__ __forceinline__ void cp16(uint32_t saddr, const void* gaddr) {
    asm volatile("cp.async.cg.shared.global [%0], [%1], 16;" :: "r"(saddr), "l"(gaddr));
}

// ---------------- zero scratch + fill constants + fp16 hi/lo cvt ----------------
__device__ __forceinline__ void cvt4(const float* __restrict__ in, int i4,
                                     __half* __restrict__ hi, __half* __restrict__ lo) {
    float4 v = ((const float4*)in)[i4];
    __half2 h0 = __floats2half2_rn(v.x, v.y);
    __half2 h1 = __floats2half2_rn(v.z, v.w);
    float2 f0 = __half22float2(h0), f1 = __half22float2(h1);
    __half2 l0 = __floats2half2_rn(v.x - f0.x, v.y - f0.y);
    __half2 l1 = __floats2half2_rn(v.z - f1.x, v.w - f1.y);
    ((uint2*)hi)[i4] = make_uint2(*(uint32_t*)&h0, *(uint32_t*)&h1);
    ((uint2*)lo)[i4] = make_uint2(*(uint32_t*)&l0, *(uint32_t*)&l1);
}

__global__ void k_zero(const float* __restrict__ h, const float* __restrict__ W1,
                       const float* __restrict__ W2,
                       const float* __restrict__ a1, const float* __restrict__ a2) {
    int idx = blockIdx.x * blockDim.x + threadIdx.x;      // 512 x 1024 = 524288
    ((uint4*)g_bitmap)[idx] = make_uint4(0u, 0u, 0u, 0u);
    cvt4(h, idx, g_hHi, g_hLo);                            // NNODES*256/4 == 524288
    float4 z = make_float4(0.f, 0.f, 0.f, 0.f);
    if (idx < 256 * 256 / 4) cvt4(W1, idx, g_w1Hi, g_w1Lo);
    if (idx < 128 * 256 / 4) cvt4(W2, idx, g_w2Hi, g_w2Lo);
    if (idx < NNODES / 4) ((int4*)g_deg)[idx] = make_int4(0, 0, 0, 0);
    if (idx < 64) ((float4*)g_colsum1)[idx] = z;
    if (idx < 32) ((float4*)g_colsum2)[idx] = z;
    if (idx < NHEAD * NNODES / 4) { ((float4*)g_s1src)[idx] = z; ((float4*)g_s1dst)[idx] = z; }
    if (idx < NNODES / 4) { ((float4*)g_s2src)[idx] = z; ((float4*)g_s2dst)[idx] = z; }
    if (blockIdx.x == 0 && threadIdx.x < 32) {
        int lane = threadIdx.x;
#pragma unroll
        for (int k = 0; k < 4; k++) {
            float s = 0.f;
            for (int d = lane; d < 128; d += 32) s += a1[k * 128 + d];
#pragma unroll
            for (int off = 16; off; off >>= 1) s += __shfl_xor_sync(0xffffffffu, s, off);
            if (lane == 0) g_fill[k] = lrelu(NEG_FILL * s);
        }
        float s = 0.f;
        for (int d = lane; d < 256; d += 32) s += a2[d];
#pragma unroll
        for (int off = 16; off; off >>= 1) s += __shfl_xor_sync(0xffffffffu, s, off);
        if (lane == 0) g_fill[4] = lrelu(NEG_FILL * s);
    }
}

// ---------------- edge dedup + direct bucket CSR ----------------
__global__ void k_mark(const int* __restrict__ src, const int* __restrict__ dst) {
    int e = blockIdx.x * blockDim.x + threadIdx.x;
    if (e >= EDGES) return;
    int s = src[e], d = dst[e];
    unsigned idx = (unsigned)s * NNODES + (unsigned)d;
    unsigned mask = 1u << (idx & 31u);
    unsigned old = atomicOr(&g_bitmap[idx >> 5], mask);
    if (!(old & mask)) {
        int slot = atomicAdd(&g_deg[s], 1);
        g_bucket[s * BCAP + slot] = d;
    }
}

// ---------------- HMMA GEMM, cp.async 2-stage pipeline + fused stats ----------------
template <int HW>
__global__ void __launch_bounds__(256) k_gemm_mma(
    const __half* __restrict__ Ahi, const __half* __restrict__ Alo,
    const __half* __restrict__ Bhi, const __half* __restrict__ Blo,
    __half* __restrict__ Ch, const float* __restrict__ avec,
    float* __restrict__ ssrc, float* __restrict__ sdst,
    float* __restrict__ colsum, int Nn)
{
    extern __shared__ char smem[];
    uint32_t sb = smem_u32(smem);
    const uint32_t STAGE = 65536;
    const uint32_t AHI = 0, ALO = 16384, BHI = 32768, BLO = 49152;
    const int tid = threadIdx.x, lane = tid & 31, wid = tid >> 5;
    const int wm = wid & 3, wn = wid >> 2;          // 4 x 2 warp grid
    const int bm = blockIdx.x * 128, bn = blockIdx.y * 128;

    float acc[2][8][4];
#pragma unroll
    for (int i = 0; i < 2; i++)
#pragma unroll
        for (int j = 0; j < 8; j++)
#pragma unroll
            for (int q = 0; q < 4; q++) acc[i][j][q] = 0.f;

    const int g = lane >> 3, lr = lane & 7;

    auto prefetch = [&](int kc, uint32_t st) {
        const __half* srcs[4] = {Ahi, Alo, Bhi, Blo};
        const uint32_t bases[4] = {AHI, ALO, BHI, BLO};
#pragma unroll
        for (int rgn = 0; rgn < 4; rgn++) {
            const __half* src = srcs[rgn];
            const int rowbase = (rgn < 2) ? bm : bn;
            const uint32_t sbase = sb + st + bases[rgn];
#pragma unroll
            for (int q = tid; q < 1024; q += 256) {
                int row = q >> 3, c = q & 7;
                cp16(sbase + row * 128 + (((c ^ (row & 7)) << 4)),
                     src + (size_t)(rowbase + row) * 256 + kc * 64 + c * 8);
            }
        }
    };

    prefetch(0, 0);
    asm volatile("cp.async.commit_group;");

    for (int kc = 0; kc < 4; kc++) {
        const uint32_t cur = (kc & 1) * STAGE;
        if (kc < 3) {
            prefetch(kc + 1, ((kc + 1) & 1) * STAGE);
            asm volatile("cp.async.commit_group;");
            asm volatile("cp.async.wait_group 1;");
        } else {
            asm volatile("cp.async.wait_group 0;");
        }
        __syncthreads();

#pragma unroll
        for (int ks = 0; ks < 4; ks++) {
            const int chunk = ks * 2 + (g >> 1);
            uint32_t ahi[2][4], alo[2][4], bhi[4][4], blo[4][4];
#pragma unroll
            for (int am = 0; am < 2; am++) {
                int row = wm * 32 + am * 16 + (g & 1) * 8 + lr;
                ldsm4(ahi[am], sw_addr(sb + cur + AHI, row, chunk));
                ldsm4(alo[am], sw_addr(sb + cur + ALO, row, chunk));
            }
#pragma unroll
            for (int bp = 0; bp < 4; bp++) {
                int row = wn * 64 + bp * 16 + (g & 1) * 8 + lr;
                ldsm4(bhi[bp], sw_addr(sb + cur + BHI, row, chunk));
                ldsm4(blo[bp], sw_addr(sb + cur + BLO, row, chunk));
            }
#pragma unroll
            for (int am = 0; am < 2; am++)
#pragma unroll
                for (int bp = 0; bp < 4; bp++) {
                    float* c0 = acc[am][bp * 2];
                    float* c1 = acc[am][bp * 2 + 1];
                    mma16816(c0, ahi[am], bhi[bp][0], bhi[bp][2]);
                    mma16816(c1, ahi[am], bhi[bp][1], bhi[bp][3]);
                    mma16816(c0, ahi[am], blo[bp][0], blo[bp][2]);
                    mma16816(c1, ahi[am], blo[bp][1], blo[bp][3]);
                    mma16816(c0, alo[am], bhi[bp][0], bhi[bp][2]);
                    mma16816(c1, alo[am], bhi[bp][1], bhi[bp][3]);
                }
        }
        __syncthreads();
    }

    // ---- epilogue: fp16 store + fused stats ----
    const int head = (bn + wn * 64) / HW;
    const int cbase = ((wn * 64) % HW) + (lane & 3) * 2;
    float aS[16], aD[16];
#pragma unroll
    for (int j = 0; j < 8; j++)
#pragma unroll
        for (int p = 0; p < 2; p++) {
            int cc = cbase + j * 8 + p;
            aS[j * 2 + p] = __ldg(&avec[head * 2 * HW + cc]);
            aD[j * 2 + p] = __ldg(&avec[head * 2 * HW + HW + cc]);
        }
    float ps[4] = {0.f, 0.f, 0.f, 0.f}, pd[4] = {0.f, 0.f, 0.f, 0.f}, cs[16];
#pragma unroll
    for (int c = 0; c < 16; c++) cs[c] = 0.f;

#pragma unroll
    for (int am = 0; am < 2; am++) {
        int r0 = bm + wm * 32 + am * 16 + (lane >> 2);
        int c0 = bn + wn * 64 + (lane & 3) * 2;
#pragma unroll
        for (int j = 0; j < 8; j++) {
            __half2 h0 = __floats2half2_rn(acc[am][j][0], acc[am][j][1]);
            __half2 h1 = __floats2half2_rn(acc[am][j][2], acc[am][j][3]);
            *(__half2*)&Ch[(size_t)r0 * Nn + c0 + j * 8]       = h0;
            *(__half2*)&Ch[(size_t)(r0 + 8) * Nn + c0 + j * 8] = h1;
#pragma unroll
            for (int q = 0; q < 4; q++) {
                float v = acc[am][j][q];
                int ridx = am * 2 + (q >> 1);
                int cidx = j * 2 + (q & 1);
                ps[ridx] = fmaf(v, aS[cidx], ps[ridx]);
                pd[ridx] = fmaf(v, aD[cidx], pd[ridx]);
                cs[cidx] += v;
            }
        }
    }
#pragma unroll
    for (int off = 1; off <= 2; off <<= 1)
#pragma unroll
        for (int r = 0; r < 4; r++) {
            ps[r] += __shfl_xor_sync(0xffffffffu, ps[r], off);
            pd[r] += __shfl_xor_sync(0xffffffffu, pd[r], off);
        }
    if ((lane & 3) == 0) {
#pragma unroll
        for (int r = 0; r < 4; r++) {
            int row = bm + wm * 32 + (r >> 1) * 16 + (lane >> 2) + (r & 1) * 8;
            atomicAdd(&ssrc[(size_t)head * NNODES + row], ps[r]);
            atomicAdd(&sdst[(size_t)head * NNODES + row], pd[r]);
        }
    }
#pragma unroll
    for (int off = 4; off <= 16; off <<= 1)
#pragma unroll
        for (int c = 0; c < 16; c++) cs[c] += __shfl_xor_sync(0xffffffffu, cs[c], off);
    if (lane < 4) {
#pragma unroll
        for (int j = 0; j < 8; j++)
#pragma unroll
            for (int p = 0; p < 2; p++) {
                int col = bn + wn * 64 + lane * 2 + j * 8 + p;
                atomicAdd(&colsum[col], cs[j * 2 + p]);
            }
    }
}

// ---------------- layer-1 aggregation v3: warp per node, full 256-dim row ----------------
// Lane owns 8 dims (16B). Weight phase: lane = edge, all 4 head weights -> padded smem.
// Accumulate: per edge 1 LDS(w) + 1 shfl(j) + 1 LDG.128 + 4 cvt + 8 FMA.
__global__ void __launch_bounds__(256) k_agg1() {
    __shared__ float sw[8][132];       // [warp][head*33 + edge]
    const int wwarp = threadIdx.x >> 5;
    const int i = blockIdx.x * 8 + wwarp;
    const int lane = threadIdx.x & 31;
    const int head = lane >> 3;
    const int deg = g_deg[i];
    const int* bkt = &g_bucket[i * BCAP];
    float o[8];
    if (deg == 0) {
        float4 c0 = *(const float4*)&g_colsum1[8 * lane];
        float4 c1 = *(const float4*)&g_colsum1[8 * lane + 4];
        o[0] = c0.x * (1.f / NNODES); o[1] = c0.y * (1.f / NNODES);
        o[2] = c0.z * (1.f / NNODES); o[3] = c0.w * (1.f / NNODES);
        o[4] = c1.x * (1.f / NNODES); o[5] = c1.y * (1.f / NNODES);
        o[6] = c1.z * (1.f / NNODES); o[7] = c1.w * (1.f / NNODES);
    } else {
        const float ss0 = g_s1src[i],              ss1 = g_s1src[NNODES + i];
        const float ss2 = g_s1src[2 * NNODES + i], ss3 = g_s1src[3 * NNODES + i];
        const float f0 = g_fill[0], f1 = g_fill[1], f2 = g_fill[2], f3 = g_fill[3];
        const float m0 = fmaxf(f0, 0.f), m1 = fmaxf(f1, 0.f);
        const float m2 = fmaxf(f2, 0.f), m3 = fmaxf(f3, 0.f);
        const float wf0 = __expf(f0 - m0), wf1 = __expf(f1 - m1);
        const float wf2 = __expf(f2 - m2), wf3 = __expf(f3 - m3);
        const __half* whrow = g_Wh1h + 8 * lane;
        float acc[8] = {0.f, 0.f, 0.f, 0.f, 0.f, 0.f, 0.f, 0.f};
        float ws0 = 0.f, ws1 = 0.f, ws2 = 0.f, ws3 = 0.f;
        const float* swp = &sw[wwarp][head * 33];
        for (int base = 0; base < deg; base += 32) {
            const int cnt = min(32, deg - base);
            int j = 0; float w0 = 0.f, w1 = 0.f, w2 = 0.f, w3 = 0.f;
            if (lane < cnt) {
                j = bkt[base + lane];
                w0 = __expf(lrelu(ss0 + g_s1dst[j]) - m0) - wf0;
                w1 = __expf(lrelu(ss1 + g_s1dst[NNODES + j]) - m1) - wf1;
                w2 = __expf(lrelu(ss2 + g_s1dst[2 * NNODES + j]) - m2) - wf2;
                w3 = __expf(lrelu(ss3 + g_s1dst[3 * NNODES + j]) - m3) - wf3;
            }
            sw[wwarp][lane]      = w0;
            sw[wwarp][33 + lane] = w1;
            sw[wwarp][66 + lane] = w2;
            sw[wwarp][99 + lane] = w3;
            __syncwarp();
            float t0 = w0, t1 = w1, t2 = w2, t3 = w3;
#pragma unroll
            for (int off = 16; off; off >>= 1) {
                t0 += __shfl_xor_sync(0xffffffffu, t0, off);
                t1 += __shfl_xor_sync(0xffffffffu, t1, off);
                t2 += __shfl_xor_sync(0xffffffffu, t2, off);
                t3 += __shfl_xor_sync(0xffffffffu, t3, off);
            }
            ws0 += t0; ws1 += t1; ws2 += t2; ws3 += t3;
            const int cnt4 = (cnt + 3) & ~3;
            for (int t = 0; t < cnt4; t += 4) {
#pragma unroll
                for (int u = 0; u < 4; u++) {
                    float wt = swp[t + u];
                    int jt = __shfl_sync(0xffffffffu, j, t + u);
                    uint4 uv = *(const uint4*)&whrow[(size_t)jt * 256];
                    float2 v0 = __half22float2(*(__half2*)&uv.x);
                    float2 v1 = __half22float2(*(__half2*)&uv.y);
                    float2 v2 = __half22float2(*(__half2*)&uv.z);
                    float2 v3 = __half22float2(*(__half2*)&uv.w);
                    acc[0] = fmaf(wt, v0.x, acc[0]); acc[1] = fmaf(wt, v0.y, acc[1]);
                    acc[2] = fmaf(wt, v1.x, acc[2]); acc[3] = fmaf(wt, v1.y, acc[3]);
                    acc[4] = fmaf(wt, v2.x, acc[4]); acc[5] = fmaf(wt, v2.y, acc[5]);
                    acc[6] = fmaf(wt, v3.x, acc[6]); acc[7] = fmaf(wt, v3.y, acc[7]);
                }
            }
            __syncwarp();
        }
        const float wfO = (head == 0) ? wf0 : (head == 1) ? wf1 : (head == 2) ? wf2 : wf3;
        const float wsO = (head == 0) ? ws0 : (head == 1) ? ws1 : (head == 2) ? ws2 : ws3;
        const float denom = wsO + (float)NNODES * wfO;
        float4 c0 = *(const float4*)&g_colsum1[8 * lane];
        float4 c1 = *(const float4*)&g_colsum1[8 * lane + 4];
        o[0] = (acc[0] + wfO * c0.x) / denom; o[1] = (acc[1] + wfO * c0.y) / denom;
        o[2] = (acc[2] + wfO * c0.z) / denom; o[3] = (acc[3] + wfO * c0.w) / denom;
        o[4] = (acc[4] + wfO * c1.x) / denom; o[5] = (acc[5] + wfO * c1.y) / denom;
        o[6] = (acc[6] + wfO * c1.z) / denom; o[7] = (acc[7] + wfO * c1.w) / denom;
    }
#pragma unroll
    for (int r = 0; r < 8; r++) o[r] = elu(o[r]);
    uint32_t hi[4], lo[4];
#pragma unroll
    for (int p = 0; p < 4; p++) {
        __half2 hh = __floats2half2_rn(o[2 * p], o[2 * p + 1]);
        float2 hf = __half22float2(hh);
        __half2 ll = __floats2half2_rn(o[2 * p] - hf.x, o[2 * p + 1] - hf.y);
        hi[p] = *(uint32_t*)&hh;
        lo[p] = *(uint32_t*)&ll;
    }
    size_t off_ = (size_t)i * 256 + 8 * lane;
    *(uint4*)&g_xHi[off_] = make_uint4(hi[0], hi[1], hi[2], hi[3]);
    *(uint4*)&g_xLo[off_] = make_uint4(lo[0], lo[1], lo[2], lo[3]);
}

// ---------------- layer-2 aggregation: warp per node ----------------
__global__ void k_agg2(float* __restrict__ out) {
    int i = (blockIdx.x * blockDim.x + threadIdx.x) >> 5;
    int lane = threadIdx.x & 31;
    if (i >= NNODES) return;
    int deg = g_deg[i];
    const int* bkt = &g_bucket[i * BCAP];
    float o[4];
    if (deg == 0) {
#pragma unroll
        for (int r = 0; r < 4; r++) o[r] = g_colsum2[4 * lane + r] * (1.f / NNODES);
    } else {
        const float ssrc = g_s2src[i];
        const float fill = g_fill[4];
        const float m = fmaxf(fill, 0.f);
        const float wf = __expf(fill - m);
        const __half* wh = &g_Wh2h[4 * lane];
        float acc[4] = {0.f, 0.f, 0.f, 0.f}, wsum = 0.f;
        for (int base = 0; base < deg; base += 32) {
            const int cnt = min(32, deg - base);
            int j = 0; float w = 0.f;
            if (lane < cnt) {
                j = bkt[base + lane];
                w = __expf(lrelu(ssrc + g_s2dst[j]) - m) - wf;
            }
            float wl = w;
#pragma unroll
            for (int off = 16; off; off >>= 1) wl += __shfl_xor_sync(0xffffffffu, wl, off);
            wsum += wl;
            const int cnt4 = (cnt + 3) & ~3;
            for (int t = 0; t < cnt4; t += 4) {
#pragma unroll
                for (int u = 0; u < 4; u++) {
                    float wt = __shfl_sync(0xffffffffu, w, t + u);
                    int jt = __shfl_sync(0xffffffffu, j, t + u);
                    uint2 uv = *(const uint2*)&wh[(size_t)jt * 128];
                    float2 va = __half22float2(*(__half2*)&uv.x);
                    float2 vb = __half22float2(*(__half2*)&uv.y);
                    acc[0] = fmaf(wt, va.x, acc[0]);
                    acc[1] = fmaf(wt, va.y, acc[1]);
                    acc[2] = fmaf(wt, vb.x, acc[2]);
                    acc[3] = fmaf(wt, vb.y, acc[3]);
                }
            }
        }
        float denom = wsum + (float)NNODES * wf;
#pragma unroll
        for (int r = 0; r < 4; r++)
            o[r] = (acc[r] + wf * g_colsum2[4 * lane + r]) / denom;
    }
#pragma unroll
    for (int r = 0; r < 4; r++)
        out[(size_t)i * 128 + 4 * lane + r] = elu(elu(o[r]));
}

// ---------------- launch ----------------
extern "C" void kernel_launch(void* const* d_in, const int* in_sizes, int n_in,
                              void* d_out, int out_size) {
    const float* h   = (const float*)d_in[0];   // [8192,256]
    const float* W1  = (const float*)d_in[1];   // [4,64,256] -> [256,256]
    const float* a1  = (const float*)d_in[2];   // [4,128]
    const float* W2  = (const float*)d_in[3];   // [128,256]
    const float* a2  = (const float*)d_in[4];   // [256]
    const int*  esrc = (const int*)d_in[5];     // [E]
    const int*  edst = (const int*)d_in[6];     // [E]
    float* out = (float*)d_out;

    float *pCs1, *pCs2, *pS1s, *pS1d, *pS2s, *pS2d;
    __half *pWh1h, *pWh2h, *phHi, *phLo, *pxHi, *pxLo, *pw1Hi, *pw1Lo, *pw2Hi, *pw2Lo;
    cudaGetSymbolAddress((void**)&pWh1h, g_Wh1h);
    cudaGetSymbolAddress((void**)&pWh2h, g_Wh2h);
    cudaGetSymbolAddress((void**)&phHi,  g_hHi);
    cudaGetSymbolAddress((void**)&phLo,  g_hLo);
    cudaGetSymbolAddress((void**)&pxHi,  g_xHi);
    cudaGetSymbolAddress((void**)&pxLo,  g_xLo);
    cudaGetSymbolAddress((void**)&pw1Hi, g_w1Hi);
    cudaGetSymbolAddress((void**)&pw1Lo, g_w1Lo);
    cudaGetSymbolAddress((void**)&pw2Hi, g_w2Hi);
    cudaGetSymbolAddress((void**)&pw2Lo, g_w2Lo);
    cudaGetSymbolAddress((void**)&pCs1,  g_colsum1);
    cudaGetSymbolAddress((void**)&pCs2,  g_colsum2);
    cudaGetSymbolAddress((void**)&pS1s,  g_s1src);
    cudaGetSymbolAddress((void**)&pS1d,  g_s1dst);
    cudaGetSymbolAddress((void**)&pS2s,  g_s2src);
    cudaGetSymbolAddress((void**)&pS2d,  g_s2dst);

    const int SMEM_SZ = 131072;   // 2-stage pipeline
    cudaFuncSetAttribute(k_gemm_mma<64>,  cudaFuncAttributeMaxDynamicSharedMemorySize, SMEM_SZ);
    cudaFuncSetAttribute(k_gemm_mma<128>, cudaFuncAttributeMaxDynamicSharedMemorySize, SMEM_SZ);

    k_zero<<<512, 1024>>>(h, W1, W2, a1, a2);
    k_mark<<<EDGES / 256, 256>>>(esrc, edst);

    // layer 1
    k_gemm_mma<64><<<dim3(64, 2), 256, SMEM_SZ>>>(phHi, phLo, pw1Hi, pw1Lo,
                                                  pWh1h, a1, pS1s, pS1d, pCs1, 256);
    k_agg1<<<1024, 256>>>();

    // layer 2
    k_gemm_mma<128><<<dim3(64, 1), 256, SMEM_SZ>>>(pxHi, pxLo, pw2Hi, pw2Lo,
                                                   pWh2h, a2, pS2s, pS2d, pCs2, 128);
    k_agg2<<<1024, 256>>>(out);
}

// round 14
// speedup vs baseline: 1.4724x; 1.0233x over previous
#include <cuda_runtime.h>
#include <cuda_fp16.h>
#include <cstdint>

#define NNODES 8192
#define EDGES  262144
#define NHEAD  4
#define NEG_FILL -9.0e15f
#define BCAP 128

// ---------------- scratch (no allocations allowed) ----------------
__device__ __half g_Wh1h[NNODES * 256];
__device__ __half g_Wh2h[NNODES * 128];
__device__ __half g_hHi [NNODES * 256];
__device__ __half g_hLo [NNODES * 256];
__device__ __half g_xHi [NNODES * 256];
__device__ __half g_xLo [NNODES * 256];
__device__ __half g_w1Hi[256 * 256];
__device__ __half g_w1Lo[256 * 256];
__device__ __half g_w2Hi[128 * 256];
__device__ __half g_w2Lo[128 * 256];
__device__ float g_s1src[NHEAD * NNODES];
__device__ float g_s1dst[NHEAD * NNODES];
__device__ float g_s2src[NNODES];
__device__ float g_s2dst[NNODES];
__device__ float g_colsum1[256];
__device__ float g_colsum2[128];
__device__ float g_fill[8];              // [0..3] layer1 heads, [4] layer2
__device__ unsigned g_bitmap[NNODES * NNODES / 32];   // 8 MB dedup bitmap
__device__ int g_deg[NNODES];
__device__ int g_bucket[NNODES * BCAP];  // 4 MB neighbor buckets

__device__ __forceinline__ float lrelu(float x) { return x > 0.f ? x : 0.2f * x; }
__device__ __forceinline__ float elu(float x)   { return x > 0.f ? x : expm1f(x); }

__device__ __forceinline__ uint32_t smem_u32(const void* p) {
    uint32_t a;
    asm("{ .reg .u64 t; cvta.to.shared.u64 t, %1; cvt.u32.u64 %0, t; }" : "=r"(a) : "l"(p));
    return a;
}
__device__ __forceinline__ void ldsm4(uint32_t* r, uint32_t addr) {
    asm volatile("ldmatrix.sync.aligned.m8n8.x4.shared.b16 {%0,%1,%2,%3}, [%4];"
                 : "=r"(r[0]), "=r"(r[1]), "=r"(r[2]), "=r"(r[3]) : "r"(addr));
}
__device__ __forceinline__ void mma16816(float* d, const uint32_t* a, uint32_t b0, uint32_t b1) {
    asm volatile("mma.sync.aligned.m16n8k16.row.col.f32.f16.f16.f32 "
                 "{%0,%1,%2,%3}, {%4,%5,%6,%7}, {%8,%9}, {%0,%1,%2,%3};"
                 : "+f"(d[0]), "+f"(d[1]), "+f"(d[2]), "+f"(d[3])
                 : "r"(a[0]), "r"(a[1]), "r"(a[2]), "r"(a[3]), "r"(b0), "r"(b1));
}
__device__ __forceinline__ uint32_t sw_addr(uint32_t base, int row, int chunk) {
    return base + row * 128 + (((chunk ^ (row & 7)) << 4));
}
__device__ __forceinline__ void cp16(uint32_t saddr, const void* gaddr) {
    asm volatile("cp.async.cg.shared.global [%0], [%1], 16;" :: "r"(saddr), "l"(gaddr));
}

// ---------------- zero scratch + fill constants + fp16 hi/lo cvt ----------------
__device__ __forceinline__ void cvt4(const float* __restrict__ in, int i4,
                                     __half* __restrict__ hi, __half* __restrict__ lo) {
    float4 v = ((const float4*)in)[i4];
    __half2 h0 = __floats2half2_rn(v.x, v.y);
    __half2 h1 = __floats2half2_rn(v.z, v.w);
    float2 f0 = __half22float2(h0), f1 = __half22float2(h1);
    __half2 l0 = __floats2half2_rn(v.x - f0.x, v.y - f0.y);
    __half2 l1 = __floats2half2_rn(v.z - f1.x, v.w - f1.y);
    ((uint2*)hi)[i4] = make_uint2(*(uint32_t*)&h0, *(uint32_t*)&h1);
    ((uint2*)lo)[i4] = make_uint2(*(uint32_t*)&l0, *(uint32_t*)&l1);
}

__global__ void k_zero(const float* __restrict__ h, const float* __restrict__ W1,
                       const float* __restrict__ W2,
                       const float* __restrict__ a1, const float* __restrict__ a2) {
    int idx = blockIdx.x * blockDim.x + threadIdx.x;      // 512 x 1024 = 524288
    ((uint4*)g_bitmap)[idx] = make_uint4(0u, 0u, 0u, 0u);
    cvt4(h, idx, g_hHi, g_hLo);                            // NNODES*256/4 == 524288
    float4 z = make_float4(0.f, 0.f, 0.f, 0.f);
    if (idx < 256 * 256 / 4) cvt4(W1, idx, g_w1Hi, g_w1Lo);
    if (idx < 128 * 256 / 4) cvt4(W2, idx, g_w2Hi, g_w2Lo);
    if (idx < NNODES / 4) ((int4*)g_deg)[idx] = make_int4(0, 0, 0, 0);
    if (idx < 64) ((float4*)g_colsum1)[idx] = z;
    if (idx < 32) ((float4*)g_colsum2)[idx] = z;
    if (idx < NHEAD * NNODES / 4) { ((float4*)g_s1src)[idx] = z; ((float4*)g_s1dst)[idx] = z; }
    if (idx < NNODES / 4) { ((float4*)g_s2src)[idx] = z; ((float4*)g_s2dst)[idx] = z; }
    if (blockIdx.x == 0 && threadIdx.x < 32) {
        int lane = threadIdx.x;
#pragma unroll
        for (int k = 0; k < 4; k++) {
            float s = 0.f;
            for (int d = lane; d < 128; d += 32) s += a1[k * 128 + d];
#pragma unroll
            for (int off = 16; off; off >>= 1) s += __shfl_xor_sync(0xffffffffu, s, off);
            if (lane == 0) g_fill[k] = lrelu(NEG_FILL * s);
        }
        float s = 0.f;
        for (int d = lane; d < 256; d += 32) s += a2[d];
#pragma unroll
        for (int off = 16; off; off >>= 1) s += __shfl_xor_sync(0xffffffffu, s, off);
        if (lane == 0) g_fill[4] = lrelu(NEG_FILL * s);
    }
}

// ---------------- edge dedup + direct bucket CSR ----------------
__global__ void k_mark(const int* __restrict__ src, const int* __restrict__ dst) {
    int e = blockIdx.x * blockDim.x + threadIdx.x;
    if (e >= EDGES) return;
    int s = src[e], d = dst[e];
    unsigned idx = (unsigned)s * NNODES + (unsigned)d;
    unsigned mask = 1u << (idx & 31u);
    unsigned old = atomicOr(&g_bitmap[idx >> 5], mask);
    if (!(old & mask)) {
        int slot = atomicAdd(&g_deg[s], 1);
        g_bucket[s * BCAP + slot] = d;
    }
}

// ---------------- HMMA GEMM, cp.async 2-stage pipeline + fused stats ----------------
template <int HW>
__global__ void __launch_bounds__(256) k_gemm_mma(
    const __half* __restrict__ Ahi, const __half* __restrict__ Alo,
    const __half* __restrict__ Bhi, const __half* __restrict__ Blo,
    __half* __restrict__ Ch, const float* __restrict__ avec,
    float* __restrict__ ssrc, float* __restrict__ sdst,
    float* __restrict__ colsum, int Nn)
{
    extern __shared__ char smem[];
    uint32_t sb = smem_u32(smem);
    const uint32_t STAGE = 65536;
    const uint32_t AHI = 0, ALO = 16384, BHI = 32768, BLO = 49152;
    const int tid = threadIdx.x, lane = tid & 31, wid = tid >> 5;
    const int wm = wid & 3, wn = wid >> 2;          // 4 x 2 warp grid
    const int bm = blockIdx.x * 128, bn = blockIdx.y * 128;

    float acc[2][8][4];
#pragma unroll
    for (int i = 0; i < 2; i++)
#pragma unroll
        for (int j = 0; j < 8; j++)
#pragma unroll
            for (int q = 0; q < 4; q++) acc[i][j][q] = 0.f;

    const int g = lane >> 3, lr = lane & 7;

    auto prefetch = [&](int kc, uint32_t st) {
        const __half* srcs[4] = {Ahi, Alo, Bhi, Blo};
        const uint32_t bases[4] = {AHI, ALO, BHI, BLO};
#pragma unroll
        for (int rgn = 0; rgn < 4; rgn++) {
            const __half* src = srcs[rgn];
            const int rowbase = (rgn < 2) ? bm : bn;
            const uint32_t sbase = sb + st + bases[rgn];
#pragma unroll
            for (int q = tid; q < 1024; q += 256) {
                int row = q >> 3, c = q & 7;
                cp16(sbase + row * 128 + (((c ^ (row & 7)) << 4)),
                     src + (size_t)(rowbase + row) * 256 + kc * 64 + c * 8);
            }
        }
    };

    prefetch(0, 0);
    asm volatile("cp.async.commit_group;");

    for (int kc = 0; kc < 4; kc++) {
        const uint32_t cur = (kc & 1) * STAGE;
        if (kc < 3) {
            prefetch(kc + 1, ((kc + 1) & 1) * STAGE);
            asm volatile("cp.async.commit_group;");
            asm volatile("cp.async.wait_group 1;");
        } else {
            asm volatile("cp.async.wait_group 0;");
        }
        __syncthreads();

#pragma unroll
        for (int ks = 0; ks < 4; ks++) {
            const int chunk = ks * 2 + (g >> 1);
            uint32_t ahi[2][4], alo[2][4], bhi[4][4], blo[4][4];
#pragma unroll
            for (int am = 0; am < 2; am++) {
                int row = wm * 32 + am * 16 + (g & 1) * 8 + lr;
                ldsm4(ahi[am], sw_addr(sb + cur + AHI, row, chunk));
                ldsm4(alo[am], sw_addr(sb + cur + ALO, row, chunk));
            }
#pragma unroll
            for (int bp = 0; bp < 4; bp++) {
                int row = wn * 64 + bp * 16 + (g & 1) * 8 + lr;
                ldsm4(bhi[bp], sw_addr(sb + cur + BHI, row, chunk));
                ldsm4(blo[bp], sw_addr(sb + cur + BLO, row, chunk));
            }
#pragma unroll
            for (int am = 0; am < 2; am++)
#pragma unroll
                for (int bp = 0; bp < 4; bp++) {
                    float* c0 = acc[am][bp * 2];
                    float* c1 = acc[am][bp * 2 + 1];
                    mma16816(c0, ahi[am], bhi[bp][0], bhi[bp][2]);
                    mma16816(c1, ahi[am], bhi[bp][1], bhi[bp][3]);
                    mma16816(c0, ahi[am], blo[bp][0], blo[bp][2]);
                    mma16816(c1, ahi[am], blo[bp][1], blo[bp][3]);
                    mma16816(c0, alo[am], bhi[bp][0], bhi[bp][2]);
                    mma16816(c1, alo[am], bhi[bp][1], bhi[bp][3]);
                }
        }
        __syncthreads();
    }

    // ---- epilogue: fp16 store + fused stats ----
    const int head = (bn + wn * 64) / HW;
    const int cbase = ((wn * 64) % HW) + (lane & 3) * 2;
    float aS[16], aD[16];
#pragma unroll
    for (int j = 0; j < 8; j++)
#pragma unroll
        for (int p = 0; p < 2; p++) {
            int cc = cbase + j * 8 + p;
            aS[j * 2 + p] = __ldg(&avec[head * 2 * HW + cc]);
            aD[j * 2 + p] = __ldg(&avec[head * 2 * HW + HW + cc]);
        }
    float ps[4] = {0.f, 0.f, 0.f, 0.f}, pd[4] = {0.f, 0.f, 0.f, 0.f}, cs[16];
#pragma unroll
    for (int c = 0; c < 16; c++) cs[c] = 0.f;

#pragma unroll
    for (int am = 0; am < 2; am++) {
        int r0 = bm + wm * 32 + am * 16 + (lane >> 2);
        int c0 = bn + wn * 64 + (lane & 3) * 2;
#pragma unroll
        for (int j = 0; j < 8; j++) {
            __half2 h0 = __floats2half2_rn(acc[am][j][0], acc[am][j][1]);
            __half2 h1 = __floats2half2_rn(acc[am][j][2], acc[am][j][3]);
            *(__half2*)&Ch[(size_t)r0 * Nn + c0 + j * 8]       = h0;
            *(__half2*)&Ch[(size_t)(r0 + 8) * Nn + c0 + j * 8] = h1;
#pragma unroll
            for (int q = 0; q < 4; q++) {
                float v = acc[am][j][q];
                int ridx = am * 2 + (q >> 1);
                int cidx = j * 2 + (q & 1);
                ps[ridx] = fmaf(v, aS[cidx], ps[ridx]);
                pd[ridx] = fmaf(v, aD[cidx], pd[ridx]);
                cs[cidx] += v;
            }
        }
    }
#pragma unroll
    for (int off = 1; off <= 2; off <<= 1)
#pragma unroll
        for (int r = 0; r < 4; r++) {
            ps[r] += __shfl_xor_sync(0xffffffffu, ps[r], off);
            pd[r] += __shfl_xor_sync(0xffffffffu, pd[r], off);
        }
    if ((lane & 3) == 0) {
#pragma unroll
        for (int r = 0; r < 4; r++) {
            int row = bm + wm * 32 + (r >> 1) * 16 + (lane >> 2) + (r & 1) * 8;
            atomicAdd(&ssrc[(size_t)head * NNODES + row], ps[r]);
            atomicAdd(&sdst[(size_t)head * NNODES + row], pd[r]);
        }
    }
#pragma unroll
    for (int off = 4; off <= 16; off <<= 1)
#pragma unroll
        for (int c = 0; c < 16; c++) cs[c] += __shfl_xor_sync(0xffffffffu, cs[c], off);
    if (lane < 4) {
#pragma unroll
        for (int j = 0; j < 8; j++)
#pragma unroll
            for (int p = 0; p < 2; p++) {
                int col = bn + wn * 64 + lane * 2 + j * 8 + p;
                atomicAdd(&colsum[col], cs[j * 2 + p]);
            }
    }
}

// ---------------- layer-1 aggregation v4: warp/node, smem (w,j), unroll 8, cg loads ----------------
__global__ void __launch_bounds__(256) k_agg1() {
    __shared__ float sw[8][132];       // [warp][head*33 + edge]
    __shared__ int   sj[8][32];        // [warp][edge]
    const int wwarp = threadIdx.x >> 5;
    const int i = blockIdx.x * 8 + wwarp;
    const int lane = threadIdx.x & 31;
    const int head = lane >> 3;
    const int deg = g_deg[i];
    const int* bkt = &g_bucket[i * BCAP];
    float o[8];
    if (deg == 0) {
        float4 c0 = *(const float4*)&g_colsum1[8 * lane];
        float4 c1 = *(const float4*)&g_colsum1[8 * lane + 4];
        o[0] = c0.x * (1.f / NNODES); o[1] = c0.y * (1.f / NNODES);
        o[2] = c0.z * (1.f / NNODES); o[3] = c0.w * (1.f / NNODES);
        o[4] = c1.x * (1.f / NNODES); o[5] = c1.y * (1.f / NNODES);
        o[6] = c1.z * (1.f / NNODES); o[7] = c1.w * (1.f / NNODES);
    } else {
        const float ss0 = g_s1src[i],              ss1 = g_s1src[NNODES + i];
        const float ss2 = g_s1src[2 * NNODES + i], ss3 = g_s1src[3 * NNODES + i];
        const float f0 = g_fill[0], f1 = g_fill[1], f2 = g_fill[2], f3 = g_fill[3];
        const float m0 = fmaxf(f0, 0.f), m1 = fmaxf(f1, 0.f);
        const float m2 = fmaxf(f2, 0.f), m3 = fmaxf(f3, 0.f);
        const float wf0 = __expf(f0 - m0), wf1 = __expf(f1 - m1);
        const float wf2 = __expf(f2 - m2), wf3 = __expf(f3 - m3);
        const __half* whrow = g_Wh1h + 8 * lane;
        float acc[8] = {0.f, 0.f, 0.f, 0.f, 0.f, 0.f, 0.f, 0.f};
        float ws0 = 0.f, ws1 = 0.f, ws2 = 0.f, ws3 = 0.f;
        const float* swp = &sw[wwarp][head * 33];
        const int* sjp = sj[wwarp];
        for (int base = 0; base < deg; base += 32) {
            const int cnt = min(32, deg - base);
            int j = 0; float w0 = 0.f, w1 = 0.f, w2 = 0.f, w3 = 0.f;
            if (lane < cnt) {
                j = bkt[base + lane];
                w0 = __expf(lrelu(ss0 + g_s1dst[j]) - m0) - wf0;
                w1 = __expf(lrelu(ss1 + g_s1dst[NNODES + j]) - m1) - wf1;
                w2 = __expf(lrelu(ss2 + g_s1dst[2 * NNODES + j]) - m2) - wf2;
                w3 = __expf(lrelu(ss3 + g_s1dst[3 * NNODES + j]) - m3) - wf3;
            }
            sw[wwarp][lane]      = w0;
            sw[wwarp][33 + lane] = w1;
            sw[wwarp][66 + lane] = w2;
            sw[wwarp][99 + lane] = w3;
            sj[wwarp][lane]      = j;
            __syncwarp();
            float t0 = w0, t1 = w1, t2 = w2, t3 = w3;
#pragma unroll
            for (int off = 16; off; off >>= 1) {
                t0 += __shfl_xor_sync(0xffffffffu, t0, off);
                t1 += __shfl_xor_sync(0xffffffffu, t1, off);
                t2 += __shfl_xor_sync(0xffffffffu, t2, off);
                t3 += __shfl_xor_sync(0xffffffffu, t3, off);
            }
            ws0 += t0; ws1 += t1; ws2 += t2; ws3 += t3;
            const int cnt8 = (cnt + 7) & ~7;
            for (int t = 0; t < cnt8; t += 8) {
                uint4 uv[8];
                float wt[8];
#pragma unroll
                for (int u = 0; u < 8; u++) {
                    wt[u] = swp[t + u];
                    int jt = sjp[t + u];
                    uv[u] = __ldcg((const uint4*)&whrow[(size_t)jt * 256]);
                }
#pragma unroll
                for (int u = 0; u < 8; u++) {
                    float2 v0 = __half22float2(*(__half2*)&uv[u].x);
                    float2 v1 = __half22float2(*(__half2*)&uv[u].y);
                    float2 v2 = __half22float2(*(__half2*)&uv[u].z);
                    float2 v3 = __half22float2(*(__half2*)&uv[u].w);
                    acc[0] = fmaf(wt[u], v0.x, acc[0]); acc[1] = fmaf(wt[u], v0.y, acc[1]);
                    acc[2] = fmaf(wt[u], v1.x, acc[2]); acc[3] = fmaf(wt[u], v1.y, acc[3]);
                    acc[4] = fmaf(wt[u], v2.x, acc[4]); acc[5] = fmaf(wt[u], v2.y, acc[5]);
                    acc[6] = fmaf(wt[u], v3.x, acc[6]); acc[7] = fmaf(wt[u], v3.y, acc[7]);
                }
            }
            __syncwarp();
        }
        const float wfO = (head == 0) ? wf0 : (head == 1) ? wf1 : (head == 2) ? wf2 : wf3;
        const float wsO = (head == 0) ? ws0 : (head == 1) ? ws1 : (head == 2) ? ws2 : ws3;
        const float denom = wsO + (float)NNODES * wfO;
        float4 c0 = *(const float4*)&g_colsum1[8 * lane];
        float4 c1 = *(const float4*)&g_colsum1[8 * lane + 4];
        o[0] = (acc[0] + wfO * c0.x) / denom; o[1] = (acc[1] + wfO * c0.y) / denom;
        o[2] = (acc[2] + wfO * c0.z) / denom; o[3] = (acc[3] + wfO * c0.w) / denom;
        o[4] = (acc[4] + wfO * c1.x) / denom; o[5] = (acc[5] + wfO * c1.y) / denom;
        o[6] = (acc[6] + wfO * c1.z) / denom; o[7] = (acc[7] + wfO * c1.w) / denom;
    }
#pragma unroll
    for (int r = 0; r < 8; r++) o[r] = elu(o[r]);
    uint32_t hi[4], lo[4];
#pragma unroll
    for (int p = 0; p < 4; p++) {
        __half2 hh = __floats2half2_rn(o[2 * p], o[2 * p + 1]);
        float2 hf = __half22float2(hh);
        __half2 ll = __floats2half2_rn(o[2 * p] - hf.x, o[2 * p + 1] - hf.y);
        hi[p] = *(uint32_t*)&hh;
        lo[p] = *(uint32_t*)&ll;
    }
    size_t off_ = (size_t)i * 256 + 8 * lane;
    *(uint4*)&g_xHi[off_] = make_uint4(hi[0], hi[1], hi[2], hi[3]);
    *(uint4*)&g_xLo[off_] = make_uint4(lo[0], lo[1], lo[2], lo[3]);
}

// ---------------- layer-2 aggregation: warp per node, unroll 8 ----------------
__global__ void k_agg2(float* __restrict__ out) {
    int i = (blockIdx.x * blockDim.x + threadIdx.x) >> 5;
    int lane = threadIdx.x & 31;
    if (i >= NNODES) return;
    int deg = g_deg[i];
    const int* bkt = &g_bucket[i * BCAP];
    float o[4];
    if (deg == 0) {
#pragma unroll
        for (int r = 0; r < 4; r++) o[r] = g_colsum2[4 * lane + r] * (1.f / NNODES);
    } else {
        const float ssrc = g_s2src[i];
        const float fill = g_fill[4];
        const float m = fmaxf(fill, 0.f);
        const float wf = __expf(fill - m);
        const __half* wh = &g_Wh2h[4 * lane];
        float acc[4] = {0.f, 0.f, 0.f, 0.f}, wsum = 0.f;
        for (int base = 0; base < deg; base += 32) {
            const int cnt = min(32, deg - base);
            int j = 0; float w = 0.f;
            if (lane < cnt) {
                j = bkt[base + lane];
                w = __expf(lrelu(ssrc + g_s2dst[j]) - m) - wf;
            }
            float wl = w;
#pragma unroll
            for (int off = 16; off; off >>= 1) wl += __shfl_xor_sync(0xffffffffu, wl, off);
            wsum += wl;
            const int cnt8 = (cnt + 7) & ~7;
            for (int t = 0; t < cnt8; t += 8) {
                uint2 uv[8];
                float wt[8];
#pragma unroll
                for (int u = 0; u < 8; u++) {
                    wt[u] = __shfl_sync(0xffffffffu, w, t + u);
                    int jt = __shfl_sync(0xffffffffu, j, t + u);
                    uv[u] = __ldcg((const uint2*)&wh[(size_t)jt * 128]);
                }
#pragma unroll
                for (int u = 0; u < 8; u++) {
                    float2 va = __half22float2(*(__half2*)&uv[u].x);
                    float2 vb = __half22float2(*(__half2*)&uv[u].y);
                    acc[0] = fmaf(wt[u], va.x, acc[0]);
                    acc[1] = fmaf(wt[u], va.y, acc[1]);
                    acc[2] = fmaf(wt[u], vb.x, acc[2]);
                    acc[3] = fmaf(wt[u], vb.y, acc[3]);
                }
            }
        }
        float denom = wsum + (float)NNODES * wf;
#pragma unroll
        for (int r = 0; r < 4; r++)
            o[r] = (acc[r] + wf * g_colsum2[4 * lane + r]) / denom;
    }
#pragma unroll
    for (int r = 0; r < 4; r++)
        out[(size_t)i * 128 + 4 * lane + r] = elu(elu(o[r]));
}

// ---------------- launch ----------------
extern "C" void kernel_launch(void* const* d_in, const int* in_sizes, int n_in,
                              void* d_out, int out_size) {
    const float* h   = (const float*)d_in[0];   // [8192,256]
    const float* W1  = (const float*)d_in[1];   // [4,64,256] -> [256,256]
    const float* a1  = (const float*)d_in[2];   // [4,128]
    const float* W2  = (const float*)d_in[3];   // [128,256]
    const float* a2  = (const float*)d_in[4];   // [256]
    const int*  esrc = (const int*)d_in[5];     // [E]
    const int*  edst = (const int*)d_in[6];     // [E]
    float* out = (float*)d_out;

    float *pCs1, *pCs2, *pS1s, *pS1d, *pS2s, *pS2d;
    __half *pWh1h, *pWh2h, *phHi, *phLo, *pxHi, *pxLo, *pw1Hi, *pw1Lo, *pw2Hi, *pw2Lo;
    cudaGetSymbolAddress((void**)&pWh1h, g_Wh1h);
    cudaGetSymbolAddress((void**)&pWh2h, g_Wh2h);
    cudaGetSymbolAddress((void**)&phHi,  g_hHi);
    cudaGetSymbolAddress((void**)&phLo,  g_hLo);
    cudaGetSymbolAddress((void**)&pxHi,  g_xHi);
    cudaGetSymbolAddress((void**)&pxLo,  g_xLo);
    cudaGetSymbolAddress((void**)&pw1Hi, g_w1Hi);
    cudaGetSymbolAddress((void**)&pw1Lo, g_w1Lo);
    cudaGetSymbolAddress((void**)&pw2Hi, g_w2Hi);
    cudaGetSymbolAddress((void**)&pw2Lo, g_w2Lo);
    cudaGetSymbolAddress((void**)&pCs1,  g_colsum1);
    cudaGetSymbolAddress((void**)&pCs2,  g_colsum2);
    cudaGetSymbolAddress((void**)&pS1s,  g_s1src);
    cudaGetSymbolAddress((void**)&pS1d,  g_s1dst);
    cudaGetSymbolAddress((void**)&pS2s,  g_s2src);
    cudaGetSymbolAddress((void**)&pS2d,  g_s2dst);

    const int SMEM_SZ = 131072;   // 2-stage pipeline
    cudaFuncSetAttribute(k_gemm_mma<64>,  cudaFuncAttributeMaxDynamicSharedMemorySize, SMEM_SZ);
    cudaFuncSetAttribute(k_gemm_mma<128>, cudaFuncAttributeMaxDynamicSharedMemorySize, SMEM_SZ);

    k_zero<<<512, 1024>>>(h, W1, W2, a1, a2);
    k_mark<<<EDGES / 256, 256>>>(esrc, edst);

    // layer 1
    k_gemm_mma<64><<<dim3(64, 2), 256, SMEM_SZ>>>(phHi, phLo, pw1Hi, pw1Lo,
                                                  pWh1h, a1, pS1s, pS1d, pCs1, 256);
    k_agg1<<<1024, 256>>>();

    // layer 2
    k_gemm_mma<128><<<dim3(64, 1), 256, SMEM_SZ>>>(pxHi, pxLo, pw2Hi, pw2Lo,
                                                   pWh2h, a2, pS2s, pS2d, pCs2, 128);
    k_agg2<<<1024, 256>>>(out);
}